// round 3
// baseline (speedup 1.0000x reference)
#include <cuda_runtime.h>
#include <cstdint>
#include <cstddef>

// ---------------------------------------------------------------------------
// AudioMamba forward on GB300 — multi-kernel fp32 pipeline.
// B=4, L=256 tokens, D=512, D_inner=1024, S=16, dt_rank=32, depth=4.
// M = B*L = 1024 rows everywhere. x_proj output width = 32+2*16 = 64.
// ---------------------------------------------------------------------------

constexpr int NS = 16;
constexpr int XDW = 64;   // dt_rank + 2*d_state

// ---- scratch (single static device buffer; no allocations allowed) --------
constexpr size_t OFF_H    = 0;
constexpr size_t OFF_XN   = OFF_H    + 1024 * 512;
constexpr size_t OFF_XZ   = OFF_XN   + 1024 * 512;
constexpr size_t OFF_U0   = OFF_XZ   + 1024 * 2048;
constexpr size_t OFF_U1   = OFF_U0   + 1024 * 1024;
constexpr size_t OFF_XD0  = OFF_U1   + 1024 * 1024;
constexpr size_t OFF_XD1  = OFF_XD0  + 1024 * XDW;
constexpr size_t OFF_DT0  = OFF_XD1  + 1024 * XDW;
constexpr size_t OFF_DT1  = OFF_DT0  + 1024 * 1024;
constexpr size_t OFF_Y0   = OFF_DT1  + 1024 * 1024;
constexpr size_t OFF_Y1   = OFF_Y0   + 1024 * 1024;
constexpr size_t OFF_YG   = OFF_Y1   + 1024 * 1024;
constexpr size_t OFF_IM   = OFF_YG   + 1024 * 1024;
constexpr size_t OFF_FEAT = OFF_IM   + 1024 * 256;
constexpr size_t OFF_C    = OFF_FEAT + 4 * 512;
constexpr size_t OFF_F1   = OFF_C    + 4 * 512;
constexpr size_t SCRATCH_FLOATS = OFF_F1 + 4 * 512;

__device__ float g_scratch[SCRATCH_FLOATS];

#define ACC_FLAG 1
#define SP_FLAG  2

// ---------------------------------------------------------------------------
// Tiled SGEMM:  C[M,N] (+)= A[M,K] * W[N,K]^T  (+ bias[n]) (softplus)
// Assumes M % BM == 0, N % BN == 0, K % BK == 0 (true for all call sites).
// grid.x = N/BN, grid.y = M/BM, 256 threads.
// ---------------------------------------------------------------------------
template <int BM, int BN, int BK, int TM, int TN>
__global__ void __launch_bounds__(256)
gemm_nt(const float* __restrict__ A, int lda,
        const float* __restrict__ W,               // (N,K) row-major packed
        float* __restrict__ C, int ldc,
        int K,
        const float* __restrict__ bias, int flags)
{
    constexpr int TX = BN / TN;
    constexpr int TY = BM / TM;
    static_assert(TX * TY == 256, "bad tile config");

    __shared__ __align__(16) float As[BK][BM + 4];
    __shared__ __align__(16) float Bs[BK][BN + 4];

    const int tid = threadIdx.x;
    const int tx  = tid % TX;
    const int ty  = tid / TX;
    const int rowBase = blockIdx.y * BM;
    const int colBase = blockIdx.x * BN;

    const float* Ab = A + (size_t)rowBase * lda;
    const float* Wb = W + (size_t)colBase * K;

    float acc[TM][TN];
#pragma unroll
    for (int i = 0; i < TM; i++)
#pragma unroll
        for (int j = 0; j < TN; j++) acc[i][j] = 0.f;

    for (int k0 = 0; k0 < K; k0 += BK) {
#pragma unroll
        for (int e = tid; e < BM * BK; e += 256) {
            int c = e % BK, r = e / BK;
            As[c][r] = Ab[(size_t)r * lda + k0 + c];
        }
#pragma unroll
        for (int e = tid; e < BN * BK; e += 256) {
            int c = e % BK, r = e / BK;
            Bs[c][r] = Wb[(size_t)r * K + k0 + c];
        }
        __syncthreads();

#pragma unroll
        for (int kk = 0; kk < BK; kk++) {
            float a[TM], bv[TN];
            if constexpr (TM % 4 == 0) {
#pragma unroll
                for (int i = 0; i < TM; i += 4) {
                    float4 v = *reinterpret_cast<const float4*>(&As[kk][ty * TM + i]);
                    a[i] = v.x; a[i + 1] = v.y; a[i + 2] = v.z; a[i + 3] = v.w;
                }
            } else {
#pragma unroll
                for (int i = 0; i < TM; i++) a[i] = As[kk][ty * TM + i];
            }
            if constexpr (TN % 4 == 0) {
#pragma unroll
                for (int j = 0; j < TN; j += 4) {
                    float4 v = *reinterpret_cast<const float4*>(&Bs[kk][tx * TN + j]);
                    bv[j] = v.x; bv[j + 1] = v.y; bv[j + 2] = v.z; bv[j + 3] = v.w;
                }
            } else {
#pragma unroll
                for (int j = 0; j < TN; j++) bv[j] = Bs[kk][tx * TN + j];
            }
#pragma unroll
            for (int i = 0; i < TM; i++)
#pragma unroll
                for (int j = 0; j < TN; j++)
                    acc[i][j] = fmaf(a[i], bv[j], acc[i][j]);
        }
        __syncthreads();
    }

#pragma unroll
    for (int i = 0; i < TM; i++) {
        int r = rowBase + ty * TM + i;
#pragma unroll
        for (int j = 0; j < TN; j++) {
            int cidx = colBase + tx * TN + j;
            float v = acc[i][j];
            if (bias) v += bias[cidx];
            if (flags & SP_FLAG) v = (v > 20.f) ? v : log1pf(__expf(v));
            float* p = C + (size_t)r * ldc + cidx;
            if (flags & ACC_FLAG) v += *p;
            *p = v;
        }
    }
}

// ---------------------------------------------------------------------------
// im2col for patch embed: out[m=(b,h,w)][k=(p,q)] = x[b,0,16h+p,16w+q]
// ---------------------------------------------------------------------------
__global__ void im2col_kernel(const float* __restrict__ x, float* __restrict__ out)
{
    int idx = blockIdx.x * 256 + threadIdx.x;          // 1024*256
    int k = idx & 255;  int m = idx >> 8;
    int q = k & 15;     int p = k >> 4;
    int w = m & 31;     int hh = (m >> 5) & 7;  int b = m >> 8;
    out[idx] = x[((size_t)(b * 128 + hh * 16 + p) << 9) + w * 16 + q];
}

// ---------------------------------------------------------------------------
// LayerNorm: one warp per row of 512.
// ---------------------------------------------------------------------------
__global__ void ln_kernel(const float* __restrict__ x, float* __restrict__ y,
                          const float* __restrict__ w, const float* __restrict__ bsh,
                          int rows)
{
    int warp = (blockIdx.x * blockDim.x + threadIdx.x) >> 5;
    int lane = threadIdx.x & 31;
    if (warp >= rows) return;
    const float* xr = x + (size_t)warp * 512;
    float v[16]; float s = 0.f, s2 = 0.f;
#pragma unroll
    for (int i = 0; i < 16; i++) {
        float t = xr[lane + i * 32];
        v[i] = t; s += t; s2 += t * t;
    }
#pragma unroll
    for (int o = 16; o; o >>= 1) {
        s  += __shfl_xor_sync(0xffffffffu, s, o);
        s2 += __shfl_xor_sync(0xffffffffu, s2, o);
    }
    float m   = s * (1.f / 512.f);
    float var = s2 * (1.f / 512.f) - m * m;
    float inv = rsqrtf(var + 1e-5f);
    float* yr = y + (size_t)warp * 512;
#pragma unroll
    for (int i = 0; i < 16; i++) {
        int c = lane + i * 32;
        yr[c] = (v[i] - m) * inv * w[c] + bsh[c];
    }
}

// ---------------------------------------------------------------------------
// Depthwise causal conv (K=4) + SiLU.  dir=1 reads the time-flipped sequence;
// u[dir] is stored in scan (flipped) coordinates.
// ---------------------------------------------------------------------------
__global__ void conv_silu_kernel(const float* __restrict__ xz,
                                 const float* __restrict__ cwf, const float* __restrict__ cbf,
                                 const float* __restrict__ cwb, const float* __restrict__ cbb,
                                 float* __restrict__ u0, float* __restrict__ u1)
{
    int idx = blockIdx.x * 256 + threadIdx.x;          // 0 .. 1M-1
    int dir = blockIdx.y;
    int d = idx & 1023;
    int r = idx >> 10;
    int l = r & 255;  int b = r >> 8;
    const float* cw = dir ? cwb : cwf;
    const float* cb = dir ? cbb : cbf;
    float acc = cb[d];
#pragma unroll
    for (int k = 0; k < 4; k++) {
        int p = l - 3 + k;
        if (p >= 0) {
            int torig = dir ? (255 - p) : p;
            acc += xz[((size_t)(b * 256 + torig) << 11) + d] * cw[d * 4 + k];
        }
    }
    float sg = 1.f / (1.f + __expf(-acc));
    (dir ? u1 : u0)[idx] = acc * sg;
}

// ---------------------------------------------------------------------------
// Selective scan: one thread per (dir, b, d) channel; sequential over L=256.
// State S=16 in registers; B/C (shared over channels) staged in smem per step.
// xd row layout (width 64): dtr [0:32], B [32:48], C [48:64].
// grid = (8, 4, 2), block = 128.
// ---------------------------------------------------------------------------
__global__ void scan_kernel(const float* __restrict__ dt0, const float* __restrict__ dt1,
                            const float* __restrict__ u0,  const float* __restrict__ u1,
                            const float* __restrict__ xd0, const float* __restrict__ xd1,
                            const float* __restrict__ Af,  const float* __restrict__ Ab,
                            const float* __restrict__ Dfp, const float* __restrict__ Dbp,
                            float* __restrict__ y0, float* __restrict__ y1)
{
    int tid = threadIdx.x;
    int d   = blockIdx.x * 128 + tid;
    int b   = blockIdx.y;
    int dir = blockIdx.z;
    const float* dt = dir ? dt1 : dt0;
    const float* u  = dir ? u1  : u0;
    const float* xd = dir ? xd1 : xd0;
    const float* Al = dir ? Ab  : Af;
    const float* Dp = dir ? Dbp : Dfp;
    float* y = dir ? y1 : y0;

    float A[NS];
#pragma unroll
    for (int s = 0; s < NS; s++) A[s] = -__expf(Al[d * NS + s]);
    float Dv = Dp[d];
    float st[NS];
#pragma unroll
    for (int s = 0; s < NS; s++) st[s] = 0.f;

    __shared__ float sBC[32];
    const size_t rowbase = (size_t)b * 256;
    for (int t = 0; t < 256; t++) {
        if (tid < 32) sBC[tid] = xd[(rowbase + t) * XDW + 32 + tid];
        __syncthreads();
        float dtv = dt[(rowbase + t) * 1024 + d];
        float uv  = u [(rowbase + t) * 1024 + d];
        float du  = dtv * uv;
        float yv  = 0.f;
#pragma unroll
        for (int s = 0; s < NS; s++) {
            float dA = __expf(dtv * A[s]);
            st[s] = st[s] * dA + du * sBC[s];
            yv   += st[s] * sBC[16 + s];
        }
        y[(rowbase + t) * 1024 + d] = yv + uv * Dv;
        __syncthreads();
    }
}

// ---------------------------------------------------------------------------
// Combine: yg = (y_f + flip_L(y_b)) * silu(z)
// ---------------------------------------------------------------------------
__global__ void gate_kernel(const float* __restrict__ y0, const float* __restrict__ y1,
                            const float* __restrict__ xz, float* __restrict__ yg)
{
    int idx = blockIdx.x * 256 + threadIdx.x;          // 1M
    int d = idx & 1023;  int r = idx >> 10;
    int l = r & 255;     int b = r >> 8;
    float z  = xz[((size_t)r << 11) + 1024 + d];
    float yv = y0[idx] + y1[(((size_t)(b * 256) + (255 - l)) << 10) + d];
    yg[idx] = yv * (z / (1.f + __expf(-z)));
}

// ---------------------------------------------------------------------------
// Mean pool over L.
// ---------------------------------------------------------------------------
__global__ void pool_kernel(const float* __restrict__ xn, float* __restrict__ feat)
{
    int idx = blockIdx.x * 256 + threadIdx.x;          // 4*512
    if (idx >= 4 * 512) return;
    int b = idx >> 9, d = idx & 511;
    float s = 0.f;
    for (int l = 0; l < 256; l++) s += xn[((size_t)(b * 256 + l) << 9) + d];
    feat[idx] = s * (1.f / 256.f);
}

// ---------------------------------------------------------------------------
// Small FC: one warp per output element, shuffle-reduced dot product.
// ---------------------------------------------------------------------------
__global__ void fc_kernel(const float* __restrict__ in, const float* __restrict__ Wt,
                          const float* __restrict__ bias, float* __restrict__ out,
                          int Brows, int N, int K, int relu)
{
    int warp = (blockIdx.x * blockDim.x + threadIdx.x) >> 5;
    int lane = threadIdx.x & 31;
    if (warp >= Brows * N) return;
    int b = warp / N, j = warp % N;
    const float* ir = in + (size_t)b * K;
    const float* wr = Wt + (size_t)j * K;
    float s = 0.f;
    for (int k = lane; k < K; k += 32) s += ir[k] * wr[k];
#pragma unroll
    for (int o = 16; o; o >>= 1) s += __shfl_xor_sync(0xffffffffu, s, o);
    if (lane == 0) {
        float v = s + bias[j];
        if (relu) v = fmaxf(v, 0.f);
        out[warp] = v;
    }
}

// ---------------------------------------------------------------------------
// kernel_launch
// ---------------------------------------------------------------------------
extern "C" void kernel_launch(void* const* d_in, const int* in_sizes, int n_in,
                              void* d_out, int out_size)
{
    float* sc = nullptr;
    cudaGetSymbolAddress((void**)&sc, g_scratch);

    auto F = [&](int i) { return (const float*)d_in[i]; };
    const float *x = F(0), *patch_w = F(1), *patch_b = F(2), *in_proj_w = F(3);
    const float *conv_w_f, *conv_b_f, *conv_w_b, *conv_b_b;
    const float *xproj_w_f, *xproj_w_b, *dtproj_w_f, *dtproj_b_f, *dtproj_w_b, *dtproj_b_b;
    const float *A_log_f, *A_log_b, *D_f, *D_b;

    if (in_sizes[6] == 16384) {
        // reference-signature order
        conv_w_f = F(4);  conv_b_f = F(5);  conv_w_b = F(6);  conv_b_b = F(7);
        xproj_w_f = F(8); xproj_w_b = F(9);
        dtproj_w_f = F(10); dtproj_b_f = F(11); dtproj_w_b = F(12); dtproj_b_b = F(13);
        A_log_f = F(14); A_log_b = F(15); D_f = F(16); D_b = F(17);
    } else {
        // setup_inputs dict order
        conv_w_f = F(4);  conv_b_f = F(5);  xproj_w_f = F(6); dtproj_w_f = F(7);
        dtproj_b_f = F(8); A_log_f = F(9);  D_f = F(10);
        conv_w_b = F(11); conv_b_b = F(12); xproj_w_b = F(13); dtproj_w_b = F(14);
        dtproj_b_b = F(15); A_log_b = F(16); D_b = F(17);
    }
    const float *out_proj_w = F(18), *norm_w = F(19), *norm_b = F(20);
    const float *normf_w = F(21), *normf_b = F(22), *ln_w = F(23), *ln_b = F(24);
    const float *fc1_w = F(25), *fc1_b = F(26), *fc2_w = F(27), *fc2_b = F(28);

    float* h_p   = sc + OFF_H;
    float* xn_p  = sc + OFF_XN;
    float* xz_p  = sc + OFF_XZ;
    float* u_p[2]  = { sc + OFF_U0,  sc + OFF_U1  };
    float* xd_p[2] = { sc + OFF_XD0, sc + OFF_XD1 };
    float* dt_p[2] = { sc + OFF_DT0, sc + OFF_DT1 };
    float* y_p[2]  = { sc + OFF_Y0,  sc + OFF_Y1  };
    float* yg_p  = sc + OFF_YG;
    float* im_p  = sc + OFF_IM;
    float* feat_p = sc + OFF_FEAT;
    float* c_p    = sc + OFF_C;
    float* f1_p   = sc + OFF_F1;

    // ---- patch embed --------------------------------------------------------
    im2col_kernel<<<1024, 256>>>(x, im_p);
    gemm_nt<64, 64, 16, 4, 4><<<dim3(512 / 64, 1024 / 64), 256>>>(
        im_p, 256, patch_w, h_p, 512, 256, patch_b, 0);

    const float* xpw[2]  = { xproj_w_f,  xproj_w_b  };
    const float* dtw[2]  = { dtproj_w_f, dtproj_w_b };
    const float* dtb[2]  = { dtproj_b_f, dtproj_b_b };

    for (int i = 0; i < 4; i++) {
        ln_kernel<<<128, 256>>>(h_p, xn_p, norm_w + i * 512, norm_b + i * 512, 1024);

        gemm_nt<128, 64, 16, 8, 4><<<dim3(2048 / 64, 1024 / 128), 256>>>(
            xn_p, 512, in_proj_w + (size_t)i * 2048 * 512, xz_p, 2048, 512, nullptr, 0);

        conv_silu_kernel<<<dim3(4096, 2), 256>>>(
            xz_p,
            conv_w_f + i * 4096, conv_b_f + i * 1024,
            conv_w_b + i * 4096, conv_b_b + i * 1024,
            u_p[0], u_p[1]);

        for (int dir = 0; dir < 2; dir++) {
            gemm_nt<64, 16, 32, 4, 1><<<dim3(XDW / 16, 1024 / 64), 256>>>(
                u_p[dir], 1024, xpw[dir] + (size_t)i * XDW * 1024, xd_p[dir], XDW, 1024,
                nullptr, 0);
            gemm_nt<128, 64, 16, 8, 4><<<dim3(1024 / 64, 1024 / 128), 256>>>(
                xd_p[dir], XDW, dtw[dir] + (size_t)i * 1024 * 32, dt_p[dir], 1024, 32,
                dtb[dir] + i * 1024, SP_FLAG);
        }

        scan_kernel<<<dim3(8, 4, 2), 128>>>(
            dt_p[0], dt_p[1], u_p[0], u_p[1], xd_p[0], xd_p[1],
            A_log_f + i * 16384, A_log_b + i * 16384,
            D_f + i * 1024, D_b + i * 1024,
            y_p[0], y_p[1]);

        gate_kernel<<<4096, 256>>>(y_p[0], y_p[1], xz_p, yg_p);

        gemm_nt<64, 64, 16, 4, 4><<<dim3(512 / 64, 1024 / 64), 256>>>(
            yg_p, 1024, out_proj_w + (size_t)i * 512 * 1024, h_p, 512, 1024,
            nullptr, ACC_FLAG);
    }

    // ---- head ---------------------------------------------------------------
    ln_kernel<<<128, 256>>>(h_p, xn_p, normf_w, normf_b, 1024);
    pool_kernel<<<8, 256>>>(xn_p, feat_p);
    ln_kernel<<<1, 256>>>(feat_p, c_p, ln_w, ln_b, 4);
    fc_kernel<<<256, 256>>>(c_p, fc1_w, fc1_b, f1_p, 4, 512, 512, 1);
    fc_kernel<<<5, 256>>>(f1_p, fc2_w, fc2_b, (float*)d_out, 4, 10, 512, 0);
}

// round 4
// speedup vs baseline: 1.6398x; 1.6398x over previous
#include <cuda_runtime.h>
#include <cstdint>
#include <cstddef>

// ---------------------------------------------------------------------------
// AudioMamba forward on GB300 — R4: SIMT overhaul.
// B=4, L=256 tokens, D=512, D_inner=1024, S=16, dt_rank=32, depth=4.
// M = B*L = 1024 rows. x_proj output width = 64.
// ---------------------------------------------------------------------------

constexpr int NS = 16;
constexpr int XDW = 64;

// ---- scratch --------------------------------------------------------------
constexpr size_t OFF_H    = 0;
constexpr size_t OFF_XN   = OFF_H    + 1024 * 512;
constexpr size_t OFF_XZ   = OFF_XN   + 1024 * 512;
constexpr size_t OFF_U0   = OFF_XZ   + 1024 * 2048;
constexpr size_t OFF_U1   = OFF_U0   + 1024 * 1024;   // must follow U0
constexpr size_t OFF_XD0  = OFF_U1   + 1024 * 1024;
constexpr size_t OFF_XD1  = OFF_XD0  + 1024 * XDW;    // must follow XD0
constexpr size_t OFF_DT0  = OFF_XD1  + 1024 * XDW;
constexpr size_t OFF_DT1  = OFF_DT0  + 1024 * 1024;   // must follow DT0
constexpr size_t OFF_Y0   = OFF_DT1  + 1024 * 1024;
constexpr size_t OFF_Y1   = OFF_Y0   + 1024 * 1024;
constexpr size_t OFF_YG   = OFF_Y1   + 1024 * 1024;
constexpr size_t OFF_IM   = OFF_YG   + 1024 * 1024;
constexpr size_t OFF_XPP  = OFF_IM   + 1024 * 256;    // xproj partials: 16 x 1024 x 64
constexpr size_t OFF_OPP  = OFF_XPP  + 16 * 1024 * 64; // outproj partials: 2 x 1024 x 512
constexpr size_t OFF_FEAT = OFF_OPP  + 2 * 1024 * 512;
constexpr size_t OFF_C    = OFF_FEAT + 4 * 512;
constexpr size_t OFF_F1   = OFF_C    + 4 * 512;
constexpr size_t SCRATCH_FLOATS = OFF_F1 + 4 * 512;

__device__ float g_scratch[SCRATCH_FLOATS];

#define ACC_FLAG 1
#define SP_FLAG  2

// ---------------------------------------------------------------------------
// Shared GEMM core: acc[TM][TN] += A[BMxK] * W[BNxK]^T over [0,kend).
// A row stride lda, W row stride ldw. 256 threads.
// ---------------------------------------------------------------------------
template <int BM, int BN, int BK, int TM, int TN>
__device__ __forceinline__ void gemm_core(const float* __restrict__ Ab, int lda,
                                          const float* __restrict__ Wb, int ldw,
                                          int kend, float (&acc)[TM][TN])
{
    constexpr int TX = BN / TN;
    constexpr int TY = BM / TM;
    static_assert(TX * TY == 256, "bad tile config");

    __shared__ __align__(16) float As[BK][BM + 4];
    __shared__ __align__(16) float Bs[BK][BN + 4];

    const int tid = threadIdx.x;
    const int tx  = tid % TX;
    const int ty  = tid / TX;

    for (int k0 = 0; k0 < kend; k0 += BK) {
#pragma unroll
        for (int e = tid; e < BM * BK; e += 256) {
            int c = e % BK, r = e / BK;
            As[c][r] = Ab[(size_t)r * lda + k0 + c];
        }
#pragma unroll
        for (int e = tid; e < BN * BK; e += 256) {
            int c = e % BK, r = e / BK;
            Bs[c][r] = Wb[(size_t)r * ldw + k0 + c];
        }
        __syncthreads();

#pragma unroll
        for (int kk = 0; kk < BK; kk++) {
            float a[TM], bv[TN];
#pragma unroll
            for (int i = 0; i < TM; i += 4) {
                float4 v = *reinterpret_cast<const float4*>(&As[kk][ty * TM + i]);
                a[i] = v.x; a[i + 1] = v.y; a[i + 2] = v.z; a[i + 3] = v.w;
            }
#pragma unroll
            for (int j = 0; j < TN; j += 4) {
                float4 v = *reinterpret_cast<const float4*>(&Bs[kk][tx * TN + j]);
                bv[j] = v.x; bv[j + 1] = v.y; bv[j + 2] = v.z; bv[j + 3] = v.w;
            }
#pragma unroll
            for (int i = 0; i < TM; i++)
#pragma unroll
                for (int j = 0; j < TN; j++)
                    acc[i][j] = fmaf(a[i], bv[j], acc[i][j]);
        }
        __syncthreads();
    }
}

// ---------------------------------------------------------------------------
// Plain GEMM: C[M,N] (+)= A*W^T (+bias)(softplus). grid (N/BN, M/BM).
// ---------------------------------------------------------------------------
template <int BM, int BN, int BK, int TM, int TN>
__global__ void __launch_bounds__(256)
gemm_plain(const float* __restrict__ A, int lda,
           const float* __restrict__ W, int ldw,
           float* __restrict__ C, int ldc, int K,
           const float* __restrict__ bias, int flags)
{
    constexpr int TX = BN / TN;
    const int tid = threadIdx.x;
    const int tx  = tid % TX;
    const int ty  = tid / TX;
    const int rowBase = blockIdx.y * BM;
    const int colBase = blockIdx.x * BN;

    float acc[TM][TN];
#pragma unroll
    for (int i = 0; i < TM; i++)
#pragma unroll
        for (int j = 0; j < TN; j++) acc[i][j] = 0.f;

    gemm_core<BM, BN, BK, TM, TN>(A + (size_t)rowBase * lda,  lda,
                                  W + (size_t)colBase * ldw, ldw, K, acc);

#pragma unroll
    for (int i = 0; i < TM; i++) {
        int r = rowBase + ty * TM + i;
#pragma unroll
        for (int j = 0; j < TN; j++) {
            int cidx = colBase + tx * TN + j;
            float v = acc[i][j];
            if (bias) v += bias[cidx];
            if (flags & SP_FLAG) v = (v > 20.f) ? v : log1pf(__expf(v));
            float* p = C + (size_t)r * ldc + cidx;
            if (flags & ACC_FLAG) v += *p;
            *p = v;
        }
    }
}

// ---------------------------------------------------------------------------
// dt GEMM, dir-batched (z = dir): dt[dir] = softplus(xd[dir][:, :32] @ dtw^T + b)
// grid (16, 16, 2). A stride between dirs = 65536, C stride = 1048576.
// ---------------------------------------------------------------------------
__global__ void __launch_bounds__(256)
gemm_dt(const float* __restrict__ xdbase,
        const float* __restrict__ W0, const float* __restrict__ W1,
        const float* __restrict__ b0, const float* __restrict__ b1,
        float* __restrict__ dtbase)
{
    constexpr int BM = 64, BN = 64, BK = 16, TM = 4, TN = 4, TX = 16;
    const int dir = blockIdx.z;
    const float* A = xdbase + (size_t)dir * (1024 * XDW);
    const float* W = dir ? W1 : W0;
    const float* bias = dir ? b1 : b0;
    float* C = dtbase + (size_t)dir * (1024 * 1024);

    const int tid = threadIdx.x;
    const int tx = tid % TX, ty = tid / TX;
    const int rowBase = blockIdx.y * BM;
    const int colBase = blockIdx.x * BN;

    float acc[TM][TN];
#pragma unroll
    for (int i = 0; i < TM; i++)
#pragma unroll
        for (int j = 0; j < TN; j++) acc[i][j] = 0.f;

    gemm_core<BM, BN, BK, TM, TN>(A + (size_t)rowBase * XDW, XDW,
                                  W + (size_t)colBase * 32, 32, 32, acc);

#pragma unroll
    for (int i = 0; i < TM; i++) {
        int r = rowBase + ty * TM + i;
#pragma unroll
        for (int j = 0; j < TN; j++) {
            int cidx = colBase + tx * TN + j;
            float v = acc[i][j] + bias[cidx];
            v = (v > 20.f) ? v : log1pf(__expf(v));
            C[(size_t)r * 1024 + cidx] = v;
        }
    }
}

// ---------------------------------------------------------------------------
// x_proj partial GEMM, split-K(8) + dir-batched.
// grid (8 kc, 16 mblk, 2 dir). Each block: 64 rows x 64 cols over K-chunk 128.
// partial[(dir*8+kc)][m][e]
// ---------------------------------------------------------------------------
__global__ void __launch_bounds__(256)
gemm_xproj_part(const float* __restrict__ ubase,
                const float* __restrict__ W0, const float* __restrict__ W1,
                float* __restrict__ partial)
{
    constexpr int BM = 64, BN = 64, BK = 16, TM = 4, TN = 4, TX = 16;
    const int kc  = blockIdx.x;
    const int dir = blockIdx.z;
    const float* A = ubase + (size_t)dir * (1024 * 1024) + kc * 128;
    const float* W = (dir ? W1 : W0) + kc * 128;

    const int tid = threadIdx.x;
    const int tx = tid % TX, ty = tid / TX;
    const int rowBase = blockIdx.y * BM;

    float acc[TM][TN];
#pragma unroll
    for (int i = 0; i < TM; i++)
#pragma unroll
        for (int j = 0; j < TN; j++) acc[i][j] = 0.f;

    gemm_core<BM, BN, BK, TM, TN>(A + (size_t)rowBase * 1024, 1024, W, 1024, 128, acc);

    float* out = partial + ((size_t)(dir * 8 + kc)) * (1024 * 64);
#pragma unroll
    for (int i = 0; i < TM; i++) {
        int r = rowBase + ty * TM + i;
#pragma unroll
        for (int j = 0; j < TN; j++)
            out[(size_t)r * 64 + tx * TN + j] = acc[i][j];
    }
}

// reduce 8 k-chunks -> xd[dir][m][e]
__global__ void xproj_reduce(const float* __restrict__ partial, float* __restrict__ xdbase)
{
    int idx = blockIdx.x * 256 + threadIdx.x;          // 2*65536
    int dir = idx >> 16;
    int rem = idx & 65535;
    float s = 0.f;
#pragma unroll
    for (int kc = 0; kc < 8; kc++)
        s += partial[((size_t)(dir * 8 + kc) << 16) + rem];
    xdbase[((size_t)dir << 16) + rem] = s;
}

// ---------------------------------------------------------------------------
// out_proj partial, split-K(2): grid (8 nblk, 16 mblk, 2 kc).
// partial[kc][m][n], K-chunk = 512.
// ---------------------------------------------------------------------------
__global__ void __launch_bounds__(256)
gemm_op_part(const float* __restrict__ yg, const float* __restrict__ Wop,
             float* __restrict__ partial)
{
    constexpr int BM = 64, BN = 64, BK = 16, TM = 4, TN = 4, TX = 16;
    const int kc = blockIdx.z;
    const float* A = yg + kc * 512;
    const float* W = Wop + kc * 512;

    const int tid = threadIdx.x;
    const int tx = tid % TX, ty = tid / TX;
    const int rowBase = blockIdx.y * BM;
    const int colBase = blockIdx.x * BN;

    float acc[TM][TN];
#pragma unroll
    for (int i = 0; i < TM; i++)
#pragma unroll
        for (int j = 0; j < TN; j++) acc[i][j] = 0.f;

    gemm_core<BM, BN, BK, TM, TN>(A + (size_t)rowBase * 1024, 1024,
                                  W + (size_t)colBase * 1024, 1024, 512, acc);

    float* out = partial + (size_t)kc * (1024 * 512);
#pragma unroll
    for (int i = 0; i < TM; i++) {
        int r = rowBase + ty * TM + i;
#pragma unroll
        for (int j = 0; j < TN; j++)
            out[(size_t)r * 512 + colBase + tx * TN + j] = acc[i][j];
    }
}

// h += p0 + p1  (residual combine)
__global__ void op_combine(const float* __restrict__ partial, float* __restrict__ h)
{
    int idx = blockIdx.x * 256 + threadIdx.x;          // 524288
    h[idx] += partial[idx] + partial[idx + 1024 * 512];
}

// ---------------------------------------------------------------------------
// im2col for patch embed
// ---------------------------------------------------------------------------
__global__ void im2col_kernel(const float* __restrict__ x, float* __restrict__ out)
{
    int idx = blockIdx.x * 256 + threadIdx.x;          // 1024*256
    int k = idx & 255;  int m = idx >> 8;
    int q = k & 15;     int p = k >> 4;
    int w = m & 31;     int hh = (m >> 5) & 7;  int b = m >> 8;
    out[idx] = x[((size_t)(b * 128 + hh * 16 + p) << 9) + w * 16 + q];
}

// ---------------------------------------------------------------------------
// LayerNorm: one warp per row of 512.
// ---------------------------------------------------------------------------
__global__ void ln_kernel(const float* __restrict__ x, float* __restrict__ y,
                          const float* __restrict__ w, const float* __restrict__ bsh,
                          int rows)
{
    int warp = (blockIdx.x * blockDim.x + threadIdx.x) >> 5;
    int lane = threadIdx.x & 31;
    if (warp >= rows) return;
    const float* xr = x + (size_t)warp * 512;
    float v[16]; float s = 0.f, s2 = 0.f;
#pragma unroll
    for (int i = 0; i < 16; i++) {
        float t = xr[lane + i * 32];
        v[i] = t; s += t; s2 += t * t;
    }
#pragma unroll
    for (int o = 16; o; o >>= 1) {
        s  += __shfl_xor_sync(0xffffffffu, s, o);
        s2 += __shfl_xor_sync(0xffffffffu, s2, o);
    }
    float m   = s * (1.f / 512.f);
    float var = s2 * (1.f / 512.f) - m * m;
    float inv = rsqrtf(var + 1e-5f);
    float* yr = y + (size_t)warp * 512;
#pragma unroll
    for (int i = 0; i < 16; i++) {
        int c = lane + i * 32;
        yr[c] = (v[i] - m) * inv * w[c] + bsh[c];
    }
}

// ---------------------------------------------------------------------------
// Depthwise causal conv (K=4) + SiLU; dir=1 operates on time-flipped sequence.
// ---------------------------------------------------------------------------
__global__ void conv_silu_kernel(const float* __restrict__ xz,
                                 const float* __restrict__ cwf, const float* __restrict__ cbf,
                                 const float* __restrict__ cwb, const float* __restrict__ cbb,
                                 float* __restrict__ u0, float* __restrict__ u1)
{
    int idx = blockIdx.x * 256 + threadIdx.x;          // 0 .. 1M-1
    int dir = blockIdx.y;
    int d = idx & 1023;
    int r = idx >> 10;
    int l = r & 255;  int b = r >> 8;
    const float* cw = dir ? cwb : cwf;
    const float* cb = dir ? cbb : cbf;
    float acc = cb[d];
#pragma unroll
    for (int k = 0; k < 4; k++) {
        int p = l - 3 + k;
        if (p >= 0) {
            int torig = dir ? (255 - p) : p;
            acc += xz[((size_t)(b * 256 + torig) << 11) + d] * cw[d * 4 + k];
        }
    }
    float sg = 1.f / (1.f + __expf(-acc));
    (dir ? u1 : u0)[idx] = acc * sg;
}

// ---------------------------------------------------------------------------
// Selective scan, time unrolled x4. grid (8,4,2), 128 threads.
// xd row (64): dtr [0:32], B [32:48], C [48:64].
// ---------------------------------------------------------------------------
__global__ void scan_kernel(const float* __restrict__ dtbase,
                            const float* __restrict__ ubase,
                            const float* __restrict__ xdbase,
                            const float* __restrict__ Af,  const float* __restrict__ Ab,
                            const float* __restrict__ Dfp, const float* __restrict__ Dbp,
                            float* __restrict__ ybase)
{
    int tid = threadIdx.x;
    int d   = blockIdx.x * 128 + tid;
    int b   = blockIdx.y;
    int dir = blockIdx.z;
    const float* dt = dtbase + (size_t)dir * (1024 * 1024);
    const float* u  = ubase  + (size_t)dir * (1024 * 1024);
    const float* xd = xdbase + (size_t)dir * (1024 * XDW);
    const float* Al = dir ? Ab  : Af;
    const float* Dp = dir ? Dbp : Dfp;
    float* y = ybase + (size_t)dir * (1024 * 1024);

    float A[NS];
#pragma unroll
    for (int s = 0; s < NS; s++) A[s] = -__expf(Al[d * NS + s]);
    float Dv = Dp[d];
    float st[NS];
#pragma unroll
    for (int s = 0; s < NS; s++) st[s] = 0.f;

    __shared__ float sBC[128];
    const size_t rowbase = (size_t)b * 256;
    for (int t0 = 0; t0 < 256; t0 += 4) {
        sBC[tid] = xd[(rowbase + t0 + (tid >> 5)) * XDW + 32 + (tid & 31)];
        __syncthreads();
        float dtv[4], uv[4];
#pragma unroll
        for (int q = 0; q < 4; q++) {
            dtv[q] = dt[(rowbase + t0 + q) * 1024 + d];
            uv[q]  = u [(rowbase + t0 + q) * 1024 + d];
        }
#pragma unroll
        for (int q = 0; q < 4; q++) {
            const float* bc = sBC + q * 32;
            float du = dtv[q] * uv[q];
            float yv = 0.f;
#pragma unroll
            for (int s = 0; s < NS; s++) {
                float dA = __expf(dtv[q] * A[s]);
                st[s] = st[s] * dA + du * bc[s];
                yv   += st[s] * bc[16 + s];
            }
            y[(rowbase + t0 + q) * 1024 + d] = yv + uv[q] * Dv;
        }
        __syncthreads();
    }
}

// ---------------------------------------------------------------------------
// Combine: yg = (y_f + flip_L(y_b)) * silu(z)
// ---------------------------------------------------------------------------
__global__ void gate_kernel(const float* __restrict__ ybase,
                            const float* __restrict__ xz, float* __restrict__ yg)
{
    int idx = blockIdx.x * 256 + threadIdx.x;          // 1M
    int d = idx & 1023;  int r = idx >> 10;
    int l = r & 255;     int b = r >> 8;
    float z  = xz[((size_t)r << 11) + 1024 + d];
    float yv = ybase[idx] +
               ybase[1024 * 1024 + (((size_t)(b * 256) + (255 - l)) << 10) + d];
    yg[idx] = yv * (z / (1.f + __expf(-z)));
}

// ---------------------------------------------------------------------------
// Mean pool over L.
// ---------------------------------------------------------------------------
__global__ void pool_kernel(const float* __restrict__ xn, float* __restrict__ feat)
{
    int idx = blockIdx.x * 256 + threadIdx.x;          // 4*512
    if (idx >= 4 * 512) return;
    int b = idx >> 9, d = idx & 511;
    float s = 0.f;
    for (int l = 0; l < 256; l++) s += xn[((size_t)(b * 256 + l) << 9) + d];
    feat[idx] = s * (1.f / 256.f);
}

// ---------------------------------------------------------------------------
// Small FC: one warp per output element.
// ---------------------------------------------------------------------------
__global__ void fc_kernel(const float* __restrict__ in, const float* __restrict__ Wt,
                          const float* __restrict__ bias, float* __restrict__ out,
                          int Brows, int N, int K, int relu)
{
    int warp = (blockIdx.x * blockDim.x + threadIdx.x) >> 5;
    int lane = threadIdx.x & 31;
    if (warp >= Brows * N) return;
    int b = warp / N, j = warp % N;
    const float* ir = in + (size_t)b * K;
    const float* wr = Wt + (size_t)j * K;
    float s = 0.f;
    for (int k = lane; k < K; k += 32) s += ir[k] * wr[k];
#pragma unroll
    for (int o = 16; o; o >>= 1) s += __shfl_xor_sync(0xffffffffu, s, o);
    if (lane == 0) {
        float v = s + bias[j];
        if (relu) v = fmaxf(v, 0.f);
        out[warp] = v;
    }
}

// ---------------------------------------------------------------------------
// kernel_launch
// ---------------------------------------------------------------------------
extern "C" void kernel_launch(void* const* d_in, const int* in_sizes, int n_in,
                              void* d_out, int out_size)
{
    float* sc = nullptr;
    cudaGetSymbolAddress((void**)&sc, g_scratch);

    auto F = [&](int i) { return (const float*)d_in[i]; };
    const float *x = F(0), *patch_w = F(1), *patch_b = F(2), *in_proj_w = F(3);
    const float *conv_w_f, *conv_b_f, *conv_w_b, *conv_b_b;
    const float *xproj_w_f, *xproj_w_b, *dtproj_w_f, *dtproj_b_f, *dtproj_w_b, *dtproj_b_b;
    const float *A_log_f, *A_log_b, *D_f, *D_b;

    if (in_sizes[6] == 16384) {
        // reference-signature order
        conv_w_f = F(4);  conv_b_f = F(5);  conv_w_b = F(6);  conv_b_b = F(7);
        xproj_w_f = F(8); xproj_w_b = F(9);
        dtproj_w_f = F(10); dtproj_b_f = F(11); dtproj_w_b = F(12); dtproj_b_b = F(13);
        A_log_f = F(14); A_log_b = F(15); D_f = F(16); D_b = F(17);
    } else {
        // setup_inputs dict order
        conv_w_f = F(4);  conv_b_f = F(5);  xproj_w_f = F(6); dtproj_w_f = F(7);
        dtproj_b_f = F(8); A_log_f = F(9);  D_f = F(10);
        conv_w_b = F(11); conv_b_b = F(12); xproj_w_b = F(13); dtproj_w_b = F(14);
        dtproj_b_b = F(15); A_log_b = F(16); D_b = F(17);
    }
    const float *out_proj_w = F(18), *norm_w = F(19), *norm_b = F(20);
    const float *normf_w = F(21), *normf_b = F(22), *ln_w = F(23), *ln_b = F(24);
    const float *fc1_w = F(25), *fc1_b = F(26), *fc2_w = F(27), *fc2_b = F(28);

    float* h_p    = sc + OFF_H;
    float* xn_p   = sc + OFF_XN;
    float* xz_p   = sc + OFF_XZ;
    float* u_p    = sc + OFF_U0;    // [2][1024][1024]
    float* xd_p   = sc + OFF_XD0;   // [2][1024][64]
    float* dt_p   = sc + OFF_DT0;   // [2][1024][1024]
    float* y_p    = sc + OFF_Y0;    // [2][1024][1024]
    float* yg_p   = sc + OFF_YG;
    float* im_p   = sc + OFF_IM;
    float* xpp_p  = sc + OFF_XPP;
    float* opp_p  = sc + OFF_OPP;
    float* feat_p = sc + OFF_FEAT;
    float* c_p    = sc + OFF_C;
    float* f1_p   = sc + OFF_F1;

    // ---- patch embed --------------------------------------------------------
    im2col_kernel<<<1024, 256>>>(x, im_p);
    gemm_plain<64, 64, 16, 4, 4><<<dim3(8, 16), 256>>>(
        im_p, 256, patch_w, 256, h_p, 512, 256, patch_b, 0);

    for (int i = 0; i < 4; i++) {
        ln_kernel<<<128, 256>>>(h_p, xn_p, norm_w + i * 512, norm_b + i * 512, 1024);

        // in_proj: 1024 x 2048 x 512
        gemm_plain<64, 64, 16, 4, 4><<<dim3(32, 16), 256>>>(
            xn_p, 512, in_proj_w + (size_t)i * 2048 * 512, 512, xz_p, 2048, 512,
            nullptr, 0);

        conv_silu_kernel<<<dim3(4096, 2), 256>>>(
            xz_p,
            conv_w_f + i * 4096, conv_b_f + i * 1024,
            conv_w_b + i * 4096, conv_b_b + i * 1024,
            u_p, u_p + 1024 * 1024);

        // x_proj: split-K(8), dir-batched
        gemm_xproj_part<<<dim3(8, 16, 2), 256>>>(
            u_p, xproj_w_f + (size_t)i * XDW * 1024, xproj_w_b + (size_t)i * XDW * 1024,
            xpp_p);
        xproj_reduce<<<512, 256>>>(xpp_p, xd_p);

        // dt_proj (+softplus), dir-batched
        gemm_dt<<<dim3(16, 16, 2), 256>>>(
            xd_p,
            dtproj_w_f + (size_t)i * 1024 * 32, dtproj_w_b + (size_t)i * 1024 * 32,
            dtproj_b_f + i * 1024, dtproj_b_b + i * 1024,
            dt_p);

        scan_kernel<<<dim3(8, 4, 2), 128>>>(
            dt_p, u_p, xd_p,
            A_log_f + i * 16384, A_log_b + i * 16384,
            D_f + i * 1024, D_b + i * 1024,
            y_p);

        gate_kernel<<<4096, 256>>>(y_p, xz_p, yg_p);

        // out_proj: split-K(2) + residual combine
        gemm_op_part<<<dim3(8, 16, 2), 256>>>(
            yg_p, out_proj_w + (size_t)i * 512 * 1024, opp_p);
        op_combine<<<2048, 256>>>(opp_p, h_p);
    }

    // ---- head ---------------------------------------------------------------
    ln_kernel<<<128, 256>>>(h_p, xn_p, normf_w, normf_b, 1024);
    pool_kernel<<<8, 256>>>(xn_p, feat_p);
    ln_kernel<<<1, 256>>>(feat_p, c_p, ln_w, ln_b, 4);
    fc_kernel<<<256, 256>>>(c_p, fc1_w, fc1_b, f1_p, 4, 512, 512, 1);
    fc_kernel<<<5, 256>>>(f1_p, fc2_w, fc2_b, (float*)d_out, 4, 10, 512, 0);
}

// round 5
// speedup vs baseline: 2.6459x; 1.6136x over previous
#include <cuda_runtime.h>
#include <cstdint>
#include <cstddef>

// ---------------------------------------------------------------------------
// AudioMamba forward on GB300 — R5: tf32 mma.sync GEMMs.
// B=4, L=256 tokens, D=512, D_inner=1024, S=16, dt_rank=32, depth=4.
// ---------------------------------------------------------------------------

constexpr int NS = 16;
constexpr int XDW = 64;

// ---- scratch --------------------------------------------------------------
constexpr size_t OFF_H    = 0;
constexpr size_t OFF_XN   = OFF_H    + 1024 * 512;
constexpr size_t OFF_XZ   = OFF_XN   + 1024 * 512;
constexpr size_t OFF_U0   = OFF_XZ   + 1024 * 2048;
constexpr size_t OFF_U1   = OFF_U0   + 1024 * 1024;
constexpr size_t OFF_XD0  = OFF_U1   + 1024 * 1024;
constexpr size_t OFF_XD1  = OFF_XD0  + 1024 * XDW;
constexpr size_t OFF_DT0  = OFF_XD1  + 1024 * XDW;
constexpr size_t OFF_DT1  = OFF_DT0  + 1024 * 1024;
constexpr size_t OFF_Y0   = OFF_DT1  + 1024 * 1024;
constexpr size_t OFF_Y1   = OFF_Y0   + 1024 * 1024;
constexpr size_t OFF_YG   = OFF_Y1   + 1024 * 1024;
constexpr size_t OFF_IM   = OFF_YG   + 1024 * 1024;
constexpr size_t OFF_XPP  = OFF_IM   + 1024 * 256;
constexpr size_t OFF_OPP  = OFF_XPP  + 16 * 1024 * 64;
constexpr size_t OFF_FEAT = OFF_OPP  + 2 * 1024 * 512;
constexpr size_t OFF_C    = OFF_FEAT + 4 * 512;
constexpr size_t OFF_F1   = OFF_C    + 4 * 512;
constexpr size_t SCRATCH_FLOATS = OFF_F1 + 4 * 512;

__device__ __align__(16) float g_scratch[SCRATCH_FLOATS];

// ---------------------------------------------------------------------------
// tf32 helpers
// ---------------------------------------------------------------------------
__device__ __forceinline__ float f2tf32(float f) {
    uint32_t u;
    asm("cvt.rna.tf32.f32 %0, %1;" : "=r"(u) : "f"(f));
    return __uint_as_float(u);
}

__device__ __forceinline__ void mma_tf32(float& c0, float& c1, float& c2, float& c3,
                                         uint32_t a0, uint32_t a1, uint32_t a2, uint32_t a3,
                                         uint32_t b0, uint32_t b1)
{
    asm volatile(
        "mma.sync.aligned.m16n8k8.row.col.f32.tf32.tf32.f32 "
        "{%0,%1,%2,%3}, {%4,%5,%6,%7}, {%8,%9}, {%0,%1,%2,%3};\n"
        : "+f"(c0), "+f"(c1), "+f"(c2), "+f"(c3)
        : "r"(a0), "r"(a1), "r"(a2), "r"(a3), "r"(b0), "r"(b1));
}

// ---------------------------------------------------------------------------
// tf32 MMA core: 64x64 block tile, BK=16, 256 threads (8 warps of 16x32).
// acc[nt][0..3]: nt = n-tile (8 cols each); C frag: c0(r,c) c1(r,c+1)
// c2(r+8,c) c3(r+8,c+1) with r = wy*16 + lane/4, c = wx*32 + nt*8 + 2*(lane%4).
// A: BM x K row-major (lda), W: BN x K row-major (ldw) == B col-major.
// ---------------------------------------------------------------------------
__device__ __forceinline__ void mma_core64(const float* __restrict__ Ab, int lda,
                                           const float* __restrict__ Wb, int ldw,
                                           int kend, float (&acc)[4][4])
{
    __shared__ __align__(16) float As[64][20];
    __shared__ __align__(16) float Bs[64][20];

    const int tid  = threadIdx.x;
    const int warp = tid >> 5, lane = tid & 31;
    const int wy = warp >> 1, wx = warp & 1;
    const int g = lane >> 2, t = lane & 3;

    const int lr = tid >> 2;           // 0..63 load row
    const int lc = (tid & 3) * 4;      // 0,4,8,12

    for (int k0 = 0; k0 < kend; k0 += 16) {
        float4 va = *reinterpret_cast<const float4*>(Ab + (size_t)lr * lda + k0 + lc);
        float4 vb = *reinterpret_cast<const float4*>(Wb + (size_t)lr * ldw + k0 + lc);
        float4 ca = make_float4(f2tf32(va.x), f2tf32(va.y), f2tf32(va.z), f2tf32(va.w));
        float4 cb = make_float4(f2tf32(vb.x), f2tf32(vb.y), f2tf32(vb.z), f2tf32(vb.w));
        *reinterpret_cast<float4*>(&As[lr][lc]) = ca;
        *reinterpret_cast<float4*>(&Bs[lr][lc]) = cb;
        __syncthreads();

#pragma unroll
        for (int k8 = 0; k8 < 16; k8 += 8) {
            const int ar = wy * 16 + g;
            uint32_t a0 = __float_as_uint(As[ar][k8 + t]);
            uint32_t a1 = __float_as_uint(As[ar + 8][k8 + t]);
            uint32_t a2 = __float_as_uint(As[ar][k8 + t + 4]);
            uint32_t a3 = __float_as_uint(As[ar + 8][k8 + t + 4]);
#pragma unroll
            for (int nt = 0; nt < 4; nt++) {
                const int bn = wx * 32 + nt * 8 + g;
                uint32_t b0 = __float_as_uint(Bs[bn][k8 + t]);
                uint32_t b1 = __float_as_uint(Bs[bn][k8 + t + 4]);
                mma_tf32(acc[nt][0], acc[nt][1], acc[nt][2], acc[nt][3],
                         a0, a1, a2, a3, b0, b1);
            }
        }
        __syncthreads();
    }
}

#define MMA_PROLOGUE                                              \
    const int warp = threadIdx.x >> 5, lane = threadIdx.x & 31;   \
    const int wy = warp >> 1, wx = warp & 1;                      \
    const int g = lane >> 2, t = lane & 3;                        \
    float acc[4][4];                                              \
    _Pragma("unroll")                                             \
    for (int i = 0; i < 4; i++)                                   \
        _Pragma("unroll")                                         \
        for (int j = 0; j < 4; j++) acc[i][j] = 0.f;

// ---------------------------------------------------------------------------
// Plain tf32 GEMM: C[M,N] = A*W^T (+bias). grid (N/64, M/64).
// ---------------------------------------------------------------------------
__global__ void __launch_bounds__(256)
gemm32_plain(const float* __restrict__ A, int lda,
             const float* __restrict__ W, int ldw,
             float* __restrict__ C, int ldc, int K,
             const float* __restrict__ bias)
{
    const int rowBase = blockIdx.y * 64;
    const int colBase = blockIdx.x * 64;
    MMA_PROLOGUE
    mma_core64(A + (size_t)rowBase * lda, lda, W + (size_t)colBase * ldw, ldw, K, acc);

    const int r0 = rowBase + wy * 16 + g;
#pragma unroll
    for (int nt = 0; nt < 4; nt++) {
        int cb = colBase + wx * 32 + nt * 8 + 2 * t;
        float v0 = acc[nt][0], v1 = acc[nt][1], v2 = acc[nt][2], v3 = acc[nt][3];
        if (bias) { v0 += bias[cb]; v1 += bias[cb + 1]; v2 += bias[cb]; v3 += bias[cb + 1]; }
        *reinterpret_cast<float2*>(&C[(size_t)r0 * ldc + cb])       = make_float2(v0, v1);
        *reinterpret_cast<float2*>(&C[(size_t)(r0 + 8) * ldc + cb]) = make_float2(v2, v3);
    }
}

// ---------------------------------------------------------------------------
// dt GEMM, dir-batched: dt[dir] = softplus(xd[dir][:, :32] @ W^T + b).
// grid (16, 16, 2).
// ---------------------------------------------------------------------------
__global__ void __launch_bounds__(256)
gemm32_dt(const float* __restrict__ xdbase,
          const float* __restrict__ W0, const float* __restrict__ W1,
          const float* __restrict__ b0, const float* __restrict__ b1,
          float* __restrict__ dtbase)
{
    const int dir = blockIdx.z;
    const float* A = xdbase + (size_t)dir * (1024 * XDW);
    const float* W = dir ? W1 : W0;
    const float* bias = dir ? b1 : b0;
    float* C = dtbase + (size_t)dir * (1024 * 1024);
    const int rowBase = blockIdx.y * 64;
    const int colBase = blockIdx.x * 64;
    MMA_PROLOGUE
    mma_core64(A + (size_t)rowBase * XDW, XDW, W + (size_t)colBase * 32, 32, 32, acc);

    const int r0 = rowBase + wy * 16 + g;
#pragma unroll
    for (int nt = 0; nt < 4; nt++) {
        int cb = colBase + wx * 32 + nt * 8 + 2 * t;
        float v[4] = { acc[nt][0] + bias[cb], acc[nt][1] + bias[cb + 1],
                       acc[nt][2] + bias[cb], acc[nt][3] + bias[cb + 1] };
#pragma unroll
        for (int q = 0; q < 4; q++) v[q] = (v[q] > 20.f) ? v[q] : log1pf(__expf(v[q]));
        *reinterpret_cast<float2*>(&C[(size_t)r0 * 1024 + cb])       = make_float2(v[0], v[1]);
        *reinterpret_cast<float2*>(&C[(size_t)(r0 + 8) * 1024 + cb]) = make_float2(v[2], v[3]);
    }
}

// ---------------------------------------------------------------------------
// x_proj partial, split-K(8) + dir-batched: grid (8 kc, 16 m, 2 dir).
// ---------------------------------------------------------------------------
__global__ void __launch_bounds__(256)
gemm32_xproj_part(const float* __restrict__ ubase,
                  const float* __restrict__ W0, const float* __restrict__ W1,
                  float* __restrict__ partial)
{
    const int kc  = blockIdx.x;
    const int dir = blockIdx.z;
    const float* A = ubase + (size_t)dir * (1024 * 1024) + kc * 128;
    const float* W = (dir ? W1 : W0) + kc * 128;
    const int rowBase = blockIdx.y * 64;
    MMA_PROLOGUE
    mma_core64(A + (size_t)rowBase * 1024, 1024, W, 1024, 128, acc);

    float* out = partial + ((size_t)(dir * 8 + kc)) * (1024 * 64);
    const int r0 = rowBase + wy * 16 + g;
#pragma unroll
    for (int nt = 0; nt < 4; nt++) {
        int cb = wx * 32 + nt * 8 + 2 * t;
        *reinterpret_cast<float2*>(&out[(size_t)r0 * 64 + cb])       = make_float2(acc[nt][0], acc[nt][1]);
        *reinterpret_cast<float2*>(&out[(size_t)(r0 + 8) * 64 + cb]) = make_float2(acc[nt][2], acc[nt][3]);
    }
}

__global__ void xproj_reduce(const float* __restrict__ partial, float* __restrict__ xdbase)
{
    int idx = blockIdx.x * 256 + threadIdx.x;          // 2*65536
    int dir = idx >> 16;
    int rem = idx & 65535;
    float s = 0.f;
#pragma unroll
    for (int kc = 0; kc < 8; kc++)
        s += partial[((size_t)(dir * 8 + kc) << 16) + rem];
    xdbase[((size_t)dir << 16) + rem] = s;
}

// ---------------------------------------------------------------------------
// out_proj partial, split-K(2): grid (8 n, 16 m, 2 kc).
// ---------------------------------------------------------------------------
__global__ void __launch_bounds__(256)
gemm32_op_part(const float* __restrict__ yg, const float* __restrict__ Wop,
               float* __restrict__ partial)
{
    const int kc = blockIdx.z;
    const float* A = yg + kc * 512;
    const float* W = Wop + kc * 512;
    const int rowBase = blockIdx.y * 64;
    const int colBase = blockIdx.x * 64;
    MMA_PROLOGUE
    mma_core64(A + (size_t)rowBase * 1024, 1024, W + (size_t)colBase * 1024, 1024, 512, acc);

    float* out = partial + (size_t)kc * (1024 * 512);
    const int r0 = rowBase + wy * 16 + g;
#pragma unroll
    for (int nt = 0; nt < 4; nt++) {
        int cb = colBase + wx * 32 + nt * 8 + 2 * t;
        *reinterpret_cast<float2*>(&out[(size_t)r0 * 512 + cb])       = make_float2(acc[nt][0], acc[nt][1]);
        *reinterpret_cast<float2*>(&out[(size_t)(r0 + 8) * 512 + cb]) = make_float2(acc[nt][2], acc[nt][3]);
    }
}

__global__ void op_combine(const float* __restrict__ partial, float* __restrict__ h)
{
    int idx = blockIdx.x * 256 + threadIdx.x;          // 524288
    h[idx] += partial[idx] + partial[idx + 1024 * 512];
}

// ---------------------------------------------------------------------------
// im2col for patch embed
// ---------------------------------------------------------------------------
__global__ void im2col_kernel(const float* __restrict__ x, float* __restrict__ out)
{
    int idx = blockIdx.x * 256 + threadIdx.x;          // 1024*256
    int k = idx & 255;  int m = idx >> 8;
    int q = k & 15;     int p = k >> 4;
    int w = m & 31;     int hh = (m >> 5) & 7;  int b = m >> 8;
    out[idx] = x[((size_t)(b * 128 + hh * 16 + p) << 9) + w * 16 + q];
}

// ---------------------------------------------------------------------------
// LayerNorm: one warp per row of 512.
// ---------------------------------------------------------------------------
__global__ void ln_kernel(const float* __restrict__ x, float* __restrict__ y,
                          const float* __restrict__ w, const float* __restrict__ bsh,
                          int rows)
{
    int warp = (blockIdx.x * blockDim.x + threadIdx.x) >> 5;
    int lane = threadIdx.x & 31;
    if (warp >= rows) return;
    const float* xr = x + (size_t)warp * 512;
    float v[16]; float s = 0.f, s2 = 0.f;
#pragma unroll
    for (int i = 0; i < 16; i++) {
        float tv = xr[lane + i * 32];
        v[i] = tv; s += tv; s2 += tv * tv;
    }
#pragma unroll
    for (int o = 16; o; o >>= 1) {
        s  += __shfl_xor_sync(0xffffffffu, s, o);
        s2 += __shfl_xor_sync(0xffffffffu, s2, o);
    }
    float m   = s * (1.f / 512.f);
    float var = s2 * (1.f / 512.f) - m * m;
    float inv = rsqrtf(var + 1e-5f);
    float* yr = y + (size_t)warp * 512;
#pragma unroll
    for (int i = 0; i < 16; i++) {
        int c = lane + i * 32;
        yr[c] = (v[i] - m) * inv * w[c] + bsh[c];
    }
}

// ---------------------------------------------------------------------------
// Depthwise causal conv (K=4) + SiLU; dir=1 operates on time-flipped sequence.
// ---------------------------------------------------------------------------
__global__ void conv_silu_kernel(const float* __restrict__ xz,
                                 const float* __restrict__ cwf, const float* __restrict__ cbf,
                                 const float* __restrict__ cwb, const float* __restrict__ cbb,
                                 float* __restrict__ u0, float* __restrict__ u1)
{
    int idx = blockIdx.x * 256 + threadIdx.x;          // 0 .. 1M-1
    int dir = blockIdx.y;
    int d = idx & 1023;
    int r = idx >> 10;
    int l = r & 255;  int b = r >> 8;
    const float* cw = dir ? cwb : cwf;
    const float* cb = dir ? cbb : cbf;
    float acc = cb[d];
#pragma unroll
    for (int k = 0; k < 4; k++) {
        int p = l - 3 + k;
        if (p >= 0) {
            int torig = dir ? (255 - p) : p;
            acc += xz[((size_t)(b * 256 + torig) << 11) + d] * cw[d * 4 + k];
        }
    }
    float sg = 1.f / (1.f + __expf(-acc));
    (dir ? u1 : u0)[idx] = acc * sg;
}

// ---------------------------------------------------------------------------
// Selective scan, time unrolled x4. grid (8,4,2), 128 threads.
// ---------------------------------------------------------------------------
__global__ void scan_kernel(const float* __restrict__ dtbase,
                            const float* __restrict__ ubase,
                            const float* __restrict__ xdbase,
                            const float* __restrict__ Af,  const float* __restrict__ Ab,
                            const float* __restrict__ Dfp, const float* __restrict__ Dbp,
                            float* __restrict__ ybase)
{
    int tid = threadIdx.x;
    int d   = blockIdx.x * 128 + tid;
    int b   = blockIdx.y;
    int dir = blockIdx.z;
    const float* dt = dtbase + (size_t)dir * (1024 * 1024);
    const float* u  = ubase  + (size_t)dir * (1024 * 1024);
    const float* xd = xdbase + (size_t)dir * (1024 * XDW);
    const float* Al = dir ? Ab  : Af;
    const float* Dp = dir ? Dbp : Dfp;
    float* y = ybase + (size_t)dir * (1024 * 1024);

    float A[NS];
#pragma unroll
    for (int s = 0; s < NS; s++) A[s] = -__expf(Al[d * NS + s]);
    float Dv = Dp[d];
    float st[NS];
#pragma unroll
    for (int s = 0; s < NS; s++) st[s] = 0.f;

    __shared__ float sBC[128];
    const size_t rowbase = (size_t)b * 256;
    for (int t0 = 0; t0 < 256; t0 += 4) {
        sBC[tid] = xd[(rowbase + t0 + (tid >> 5)) * XDW + 32 + (tid & 31)];
        __syncthreads();
        float dtv[4], uv[4];
#pragma unroll
        for (int q = 0; q < 4; q++) {
            dtv[q] = dt[(rowbase + t0 + q) * 1024 + d];
            uv[q]  = u [(rowbase + t0 + q) * 1024 + d];
        }
#pragma unroll
        for (int q = 0; q < 4; q++) {
            const float* bc = sBC + q * 32;
            float du = dtv[q] * uv[q];
            float yv = 0.f;
#pragma unroll
            for (int s = 0; s < NS; s++) {
                float dA = __expf(dtv[q] * A[s]);
                st[s] = st[s] * dA + du * bc[s];
                yv   += st[s] * bc[16 + s];
            }
            y[(rowbase + t0 + q) * 1024 + d] = yv + uv[q] * Dv;
        }
        __syncthreads();
    }
}

// ---------------------------------------------------------------------------
// Combine: yg = (y_f + flip_L(y_b)) * silu(z)
// ---------------------------------------------------------------------------
__global__ void gate_kernel(const float* __restrict__ ybase,
                            const float* __restrict__ xz, float* __restrict__ yg)
{
    int idx = blockIdx.x * 256 + threadIdx.x;          // 1M
    int d = idx & 1023;  int r = idx >> 10;
    int l = r & 255;     int b = r >> 8;
    float z  = xz[((size_t)r << 11) + 1024 + d];
    float yv = ybase[idx] +
               ybase[1024 * 1024 + (((size_t)(b * 256) + (255 - l)) << 10) + d];
    yg[idx] = yv * (z / (1.f + __expf(-z)));
}

// ---------------------------------------------------------------------------
// Mean pool over L.
// ---------------------------------------------------------------------------
__global__ void pool_kernel(const float* __restrict__ xn, float* __restrict__ feat)
{
    int idx = blockIdx.x * 256 + threadIdx.x;          // 4*512
    if (idx >= 4 * 512) return;
    int b = idx >> 9, d = idx & 511;
    float s = 0.f;
    for (int l = 0; l < 256; l++) s += xn[((size_t)(b * 256 + l) << 9) + d];
    feat[idx] = s * (1.f / 256.f);
}

// ---------------------------------------------------------------------------
// Small FC: one warp per output element.
// ---------------------------------------------------------------------------
__global__ void fc_kernel(const float* __restrict__ in, const float* __restrict__ Wt,
                          const float* __restrict__ bias, float* __restrict__ out,
                          int Brows, int N, int K, int relu)
{
    int warp = (blockIdx.x * blockDim.x + threadIdx.x) >> 5;
    int lane = threadIdx.x & 31;
    if (warp >= Brows * N) return;
    int b = warp / N, j = warp % N;
    const float* ir = in + (size_t)b * K;
    const float* wr = Wt + (size_t)j * K;
    float s = 0.f;
    for (int k = lane; k < K; k += 32) s += ir[k] * wr[k];
#pragma unroll
    for (int o = 16; o; o >>= 1) s += __shfl_xor_sync(0xffffffffu, s, o);
    if (lane == 0) {
        float v = s + bias[j];
        if (relu) v = fmaxf(v, 0.f);
        out[warp] = v;
    }
}

// ---------------------------------------------------------------------------
// kernel_launch
// ---------------------------------------------------------------------------
extern "C" void kernel_launch(void* const* d_in, const int* in_sizes, int n_in,
                              void* d_out, int out_size)
{
    float* sc = nullptr;
    cudaGetSymbolAddress((void**)&sc, g_scratch);

    auto F = [&](int i) { return (const float*)d_in[i]; };
    const float *x = F(0), *patch_w = F(1), *patch_b = F(2), *in_proj_w = F(3);
    const float *conv_w_f, *conv_b_f, *conv_w_b, *conv_b_b;
    const float *xproj_w_f, *xproj_w_b, *dtproj_w_f, *dtproj_b_f, *dtproj_w_b, *dtproj_b_b;
    const float *A_log_f, *A_log_b, *D_f, *D_b;

    if (in_sizes[6] == 16384) {
        conv_w_f = F(4);  conv_b_f = F(5);  conv_w_b = F(6);  conv_b_b = F(7);
        xproj_w_f = F(8); xproj_w_b = F(9);
        dtproj_w_f = F(10); dtproj_b_f = F(11); dtproj_w_b = F(12); dtproj_b_b = F(13);
        A_log_f = F(14); A_log_b = F(15); D_f = F(16); D_b = F(17);
    } else {
        conv_w_f = F(4);  conv_b_f = F(5);  xproj_w_f = F(6); dtproj_w_f = F(7);
        dtproj_b_f = F(8); A_log_f = F(9);  D_f = F(10);
        conv_w_b = F(11); conv_b_b = F(12); xproj_w_b = F(13); dtproj_w_b = F(14);
        dtproj_b_b = F(15); A_log_b = F(16); D_b = F(17);
    }
    const float *out_proj_w = F(18), *norm_w = F(19), *norm_b = F(20);
    const float *normf_w = F(21), *normf_b = F(22), *ln_w = F(23), *ln_b = F(24);
    const float *fc1_w = F(25), *fc1_b = F(26), *fc2_w = F(27), *fc2_b = F(28);

    float* h_p    = sc + OFF_H;
    float* xn_p   = sc + OFF_XN;
    float* xz_p   = sc + OFF_XZ;
    float* u_p    = sc + OFF_U0;
    float* xd_p   = sc + OFF_XD0;
    float* dt_p   = sc + OFF_DT0;
    float* y_p    = sc + OFF_Y0;
    float* yg_p   = sc + OFF_YG;
    float* im_p   = sc + OFF_IM;
    float* xpp_p  = sc + OFF_XPP;
    float* opp_p  = sc + OFF_OPP;
    float* feat_p = sc + OFF_FEAT;
    float* c_p    = sc + OFF_C;
    float* f1_p   = sc + OFF_F1;

    // ---- patch embed --------------------------------------------------------
    im2col_kernel<<<1024, 256>>>(x, im_p);
    gemm32_plain<<<dim3(8, 16), 256>>>(im_p, 256, patch_w, 256, h_p, 512, 256, patch_b);

    for (int i = 0; i < 4; i++) {
        ln_kernel<<<128, 256>>>(h_p, xn_p, norm_w + i * 512, norm_b + i * 512, 1024);

        // in_proj: 1024 x 2048 x 512
        gemm32_plain<<<dim3(32, 16), 256>>>(
            xn_p, 512, in_proj_w + (size_t)i * 2048 * 512, 512, xz_p, 2048, 512, nullptr);

        conv_silu_kernel<<<dim3(4096, 2), 256>>>(
            xz_p,
            conv_w_f + i * 4096, conv_b_f + i * 1024,
            conv_w_b + i * 4096, conv_b_b + i * 1024,
            u_p, u_p + 1024 * 1024);

        gemm32_xproj_part<<<dim3(8, 16, 2), 256>>>(
            u_p, xproj_w_f + (size_t)i * XDW * 1024, xproj_w_b + (size_t)i * XDW * 1024,
            xpp_p);
        xproj_reduce<<<512, 256>>>(xpp_p, xd_p);

        gemm32_dt<<<dim3(16, 16, 2), 256>>>(
            xd_p,
            dtproj_w_f + (size_t)i * 1024 * 32, dtproj_w_b + (size_t)i * 1024 * 32,
            dtproj_b_f + i * 1024, dtproj_b_b + i * 1024,
            dt_p);

        scan_kernel<<<dim3(8, 4, 2), 128>>>(
            dt_p, u_p, xd_p,
            A_log_f + i * 16384, A_log_b + i * 16384,
            D_f + i * 1024, D_b + i * 1024,
            y_p);

        gate_kernel<<<4096, 256>>>(y_p, xz_p, yg_p);

        gemm32_op_part<<<dim3(8, 16, 2), 256>>>(
            yg_p, out_proj_w + (size_t)i * 512 * 1024, opp_p);
        op_combine<<<2048, 256>>>(opp_p, h_p);
    }

    // ---- head ---------------------------------------------------------------
    ln_kernel<<<128, 256>>>(h_p, xn_p, normf_w, normf_b, 1024);
    pool_kernel<<<8, 256>>>(xn_p, feat_p);
    ln_kernel<<<1, 256>>>(feat_p, c_p, ln_w, ln_b, 4);
    fc_kernel<<<256, 256>>>(c_p, fc1_w, fc1_b, f1_p, 4, 512, 512, 1);
    fc_kernel<<<5, 256>>>(f1_p, fc2_w, fc2_b, (float*)d_out, 4, 10, 512, 0);
}

// round 6
// speedup vs baseline: 2.7900x; 1.0545x over previous
#include <cuda_runtime.h>
#include <cstdint>
#include <cstddef>

// ---------------------------------------------------------------------------
// AudioMamba forward on GB300 — R6: double-buffered tf32 MMA + split-state scan.
// ---------------------------------------------------------------------------

constexpr int NS = 16;
constexpr int XDW = 64;

// ---- scratch --------------------------------------------------------------
constexpr size_t OFF_H    = 0;
constexpr size_t OFF_XN   = OFF_H    + 1024 * 512;
constexpr size_t OFF_XZ   = OFF_XN   + 1024 * 512;
constexpr size_t OFF_U0   = OFF_XZ   + 1024 * 2048;
constexpr size_t OFF_U1   = OFF_U0   + 1024 * 1024;
constexpr size_t OFF_XD0  = OFF_U1   + 1024 * 1024;
constexpr size_t OFF_XD1  = OFF_XD0  + 1024 * XDW;
constexpr size_t OFF_DT0  = OFF_XD1  + 1024 * XDW;
constexpr size_t OFF_DT1  = OFF_DT0  + 1024 * 1024;
constexpr size_t OFF_Y0   = OFF_DT1  + 1024 * 1024;
constexpr size_t OFF_Y1   = OFF_Y0   + 1024 * 1024;
constexpr size_t OFF_YG   = OFF_Y1   + 1024 * 1024;
constexpr size_t OFF_IM   = OFF_YG   + 1024 * 1024;
constexpr size_t OFF_XPP  = OFF_IM   + 1024 * 256;
constexpr size_t OFF_OPP  = OFF_XPP  + 16 * 1024 * 64;
constexpr size_t OFF_FEAT = OFF_OPP  + 2 * 1024 * 512;
constexpr size_t OFF_C    = OFF_FEAT + 4 * 512;
constexpr size_t OFF_F1   = OFF_C    + 4 * 512;
constexpr size_t SCRATCH_FLOATS = OFF_F1 + 4 * 512;

__device__ __align__(16) float g_scratch[SCRATCH_FLOATS];

// ---------------------------------------------------------------------------
// tf32 helpers
// ---------------------------------------------------------------------------
__device__ __forceinline__ float f2tf32(float f) {
    uint32_t u;
    asm("cvt.rna.tf32.f32 %0, %1;" : "=r"(u) : "f"(f));
    return __uint_as_float(u);
}
__device__ __forceinline__ float4 cvt4(float4 v) {
    return make_float4(f2tf32(v.x), f2tf32(v.y), f2tf32(v.z), f2tf32(v.w));
}

__device__ __forceinline__ void mma_tf32(float& c0, float& c1, float& c2, float& c3,
                                         uint32_t a0, uint32_t a1, uint32_t a2, uint32_t a3,
                                         uint32_t b0, uint32_t b1)
{
    asm volatile(
        "mma.sync.aligned.m16n8k8.row.col.f32.tf32.tf32.f32 "
        "{%0,%1,%2,%3}, {%4,%5,%6,%7}, {%8,%9}, {%0,%1,%2,%3};\n"
        : "+f"(c0), "+f"(c1), "+f"(c2), "+f"(c3)
        : "r"(a0), "r"(a1), "r"(a2), "r"(a3), "r"(b0), "r"(b1));
}

// ---------------------------------------------------------------------------
// Double-buffered tf32 MMA core: 128x64 block tile, BK=16, 256 threads.
// 8 warps: wy = warp>>1 (32 rows), wx = warp&1 (32 cols). Warp tile 32x32:
// mf in {0,1} (m16 frags), nt in {0..3} (n8 frags). acc[mf][nt][4].
// C frag mapping: c0(r,c) c1(r,c+1) c2(r+8,c) c3(r+8,c+1),
//   r = wy*32+mf*16+lane/4, c = wx*32+nt*8+2*(lane%4).
// A: BM x K row-major (lda); W: BN x K row-major (ldw) == B col-major.
// kend must be a multiple of 16.
// ---------------------------------------------------------------------------
__device__ __forceinline__ void mma_core_db(const float* __restrict__ Ab, int lda,
                                            const float* __restrict__ Wb, int ldw,
                                            int kend, float (&acc)[2][4][4])
{
    __shared__ __align__(16) float As[2][128][20];
    __shared__ __align__(16) float Bs[2][64][20];

    const int tid  = threadIdx.x;
    const int warp = tid >> 5, lane = tid & 31;
    const int wy = warp >> 1, wx = warp & 1;
    const int g = lane >> 2, t = lane & 3;

    const int arow = tid >> 1, acol = (tid & 1) * 8;   // A: 2 thr/row, 8 floats each
    const int brow = tid >> 2, bcol = (tid & 3) * 4;   // B: 4 thr/row, 4 floats each

    {
        float4 va0 = *reinterpret_cast<const float4*>(Ab + (size_t)arow * lda + acol);
        float4 va1 = *reinterpret_cast<const float4*>(Ab + (size_t)arow * lda + acol + 4);
        float4 vb  = *reinterpret_cast<const float4*>(Wb + (size_t)brow * ldw + bcol);
        *reinterpret_cast<float4*>(&As[0][arow][acol])     = cvt4(va0);
        *reinterpret_cast<float4*>(&As[0][arow][acol + 4]) = cvt4(va1);
        *reinterpret_cast<float4*>(&Bs[0][brow][bcol])     = cvt4(vb);
    }
    __syncthreads();

    const int niter = kend >> 4;
    for (int it = 0; it < niter; it++) {
        const int cur = it & 1;
        float4 pa0, pa1, pb;
        const bool more = (it + 1 < niter);
        if (more) {
            int k0 = (it + 1) << 4;
            pa0 = *reinterpret_cast<const float4*>(Ab + (size_t)arow * lda + k0 + acol);
            pa1 = *reinterpret_cast<const float4*>(Ab + (size_t)arow * lda + k0 + acol + 4);
            pb  = *reinterpret_cast<const float4*>(Wb + (size_t)brow * ldw + k0 + bcol);
        }

#pragma unroll
        for (int k8 = 0; k8 < 16; k8 += 8) {
            uint32_t a[2][4], b[4][2];
#pragma unroll
            for (int mf = 0; mf < 2; mf++) {
                const int ar = wy * 32 + mf * 16 + g;
                a[mf][0] = __float_as_uint(As[cur][ar][k8 + t]);
                a[mf][1] = __float_as_uint(As[cur][ar + 8][k8 + t]);
                a[mf][2] = __float_as_uint(As[cur][ar][k8 + t + 4]);
                a[mf][3] = __float_as_uint(As[cur][ar + 8][k8 + t + 4]);
            }
#pragma unroll
            for (int nt = 0; nt < 4; nt++) {
                const int bn = wx * 32 + nt * 8 + g;
                b[nt][0] = __float_as_uint(Bs[cur][bn][k8 + t]);
                b[nt][1] = __float_as_uint(Bs[cur][bn][k8 + t + 4]);
            }
#pragma unroll
            for (int mf = 0; mf < 2; mf++)
#pragma unroll
                for (int nt = 0; nt < 4; nt++)
                    mma_tf32(acc[mf][nt][0], acc[mf][nt][1], acc[mf][nt][2], acc[mf][nt][3],
                             a[mf][0], a[mf][1], a[mf][2], a[mf][3],
                             b[nt][0], b[nt][1]);
        }

        if (more) {
            const int nxt = cur ^ 1;
            *reinterpret_cast<float4*>(&As[nxt][arow][acol])     = cvt4(pa0);
            *reinterpret_cast<float4*>(&As[nxt][arow][acol + 4]) = cvt4(pa1);
            *reinterpret_cast<float4*>(&Bs[nxt][brow][bcol])     = cvt4(pb);
            __syncthreads();
        }
    }
}

#define MMA_PROLOGUE                                              \
    const int warp = threadIdx.x >> 5, lane = threadIdx.x & 31;   \
    const int wy = warp >> 1, wx = warp & 1;                      \
    const int g = lane >> 2, t = lane & 3;                        \
    float acc[2][4][4];                                           \
    _Pragma("unroll")                                             \
    for (int i = 0; i < 2; i++)                                   \
        _Pragma("unroll")                                         \
        for (int j = 0; j < 4; j++)                               \
            _Pragma("unroll")                                     \
            for (int q = 0; q < 4; q++) acc[i][j][q] = 0.f;

// ---------------------------------------------------------------------------
// Plain tf32 GEMM: C[M,N] = A*W^T (+bias). grid (N/64, M/128).
// ---------------------------------------------------------------------------
__global__ void __launch_bounds__(256)
gemm32_plain(const float* __restrict__ A, int lda,
             const float* __restrict__ W, int ldw,
             float* __restrict__ C, int ldc, int K,
             const float* __restrict__ bias)
{
    const int rowBase = blockIdx.y * 128;
    const int colBase = blockIdx.x * 64;
    MMA_PROLOGUE
    mma_core_db(A + (size_t)rowBase * lda, lda, W + (size_t)colBase * ldw, ldw, K, acc);

#pragma unroll
    for (int mf = 0; mf < 2; mf++) {
        const int r0 = rowBase + wy * 32 + mf * 16 + g;
#pragma unroll
        for (int nt = 0; nt < 4; nt++) {
            int cb = colBase + wx * 32 + nt * 8 + 2 * t;
            float v0 = acc[mf][nt][0], v1 = acc[mf][nt][1];
            float v2 = acc[mf][nt][2], v3 = acc[mf][nt][3];
            if (bias) { v0 += bias[cb]; v1 += bias[cb + 1]; v2 += bias[cb]; v3 += bias[cb + 1]; }
            *reinterpret_cast<float2*>(&C[(size_t)r0 * ldc + cb])       = make_float2(v0, v1);
            *reinterpret_cast<float2*>(&C[(size_t)(r0 + 8) * ldc + cb]) = make_float2(v2, v3);
        }
    }
}

// ---------------------------------------------------------------------------
// dt GEMM, dir-batched: dt[dir] = softplus(xd[dir][:, :32] @ W^T + b).
// grid (16, 8, 2).
// ---------------------------------------------------------------------------
__global__ void __launch_bounds__(256)
gemm32_dt(const float* __restrict__ xdbase,
          const float* __restrict__ W0, const float* __restrict__ W1,
          const float* __restrict__ b0, const float* __restrict__ b1,
          float* __restrict__ dtbase)
{
    const int dir = blockIdx.z;
    const float* A = xdbase + (size_t)dir * (1024 * XDW);
    const float* W = dir ? W1 : W0;
    const float* bias = dir ? b1 : b0;
    float* C = dtbase + (size_t)dir * (1024 * 1024);
    const int rowBase = blockIdx.y * 128;
    const int colBase = blockIdx.x * 64;
    MMA_PROLOGUE
    mma_core_db(A + (size_t)rowBase * XDW, XDW, W + (size_t)colBase * 32, 32, 32, acc);

#pragma unroll
    for (int mf = 0; mf < 2; mf++) {
        const int r0 = rowBase + wy * 32 + mf * 16 + g;
#pragma unroll
        for (int nt = 0; nt < 4; nt++) {
            int cb = colBase + wx * 32 + nt * 8 + 2 * t;
            float v[4] = { acc[mf][nt][0] + bias[cb], acc[mf][nt][1] + bias[cb + 1],
                           acc[mf][nt][2] + bias[cb], acc[mf][nt][3] + bias[cb + 1] };
#pragma unroll
            for (int q = 0; q < 4; q++) v[q] = (v[q] > 20.f) ? v[q] : log1pf(__expf(v[q]));
            *reinterpret_cast<float2*>(&C[(size_t)r0 * 1024 + cb])       = make_float2(v[0], v[1]);
            *reinterpret_cast<float2*>(&C[(size_t)(r0 + 8) * 1024 + cb]) = make_float2(v[2], v[3]);
        }
    }
}

// ---------------------------------------------------------------------------
// x_proj partial, split-K(8) + dir-batched: grid (8 kc, 8 m, 2 dir). N=64.
// ---------------------------------------------------------------------------
__global__ void __launch_bounds__(256)
gemm32_xproj_part(const float* __restrict__ ubase,
                  const float* __restrict__ W0, const float* __restrict__ W1,
                  float* __restrict__ partial)
{
    const int kc  = blockIdx.x;
    const int dir = blockIdx.z;
    const float* A = ubase + (size_t)dir * (1024 * 1024) + kc * 128;
    const float* W = (dir ? W1 : W0) + kc * 128;
    const int rowBase = blockIdx.y * 128;
    MMA_PROLOGUE
    mma_core_db(A + (size_t)rowBase * 1024, 1024, W, 1024, 128, acc);

    float* out = partial + ((size_t)(dir * 8 + kc)) * (1024 * 64);
#pragma unroll
    for (int mf = 0; mf < 2; mf++) {
        const int r0 = rowBase + wy * 32 + mf * 16 + g;
#pragma unroll
        for (int nt = 0; nt < 4; nt++) {
            int cb = wx * 32 + nt * 8 + 2 * t;
            *reinterpret_cast<float2*>(&out[(size_t)r0 * 64 + cb])       = make_float2(acc[mf][nt][0], acc[mf][nt][1]);
            *reinterpret_cast<float2*>(&out[(size_t)(r0 + 8) * 64 + cb]) = make_float2(acc[mf][nt][2], acc[mf][nt][3]);
        }
    }
}

__global__ void xproj_reduce(const float* __restrict__ partial, float* __restrict__ xdbase)
{
    int idx = blockIdx.x * 256 + threadIdx.x;          // 2*65536
    int dir = idx >> 16;
    int rem = idx & 65535;
    float s = 0.f;
#pragma unroll
    for (int kc = 0; kc < 8; kc++)
        s += partial[((size_t)(dir * 8 + kc) << 16) + rem];
    xdbase[((size_t)dir << 16) + rem] = s;
}

// ---------------------------------------------------------------------------
// out_proj partial, split-K(2): grid (8 n, 8 m, 2 kc).
// ---------------------------------------------------------------------------
__global__ void __launch_bounds__(256)
gemm32_op_part(const float* __restrict__ yg, const float* __restrict__ Wop,
               float* __restrict__ partial)
{
    const int kc = blockIdx.z;
    const float* A = yg + kc * 512;
    const float* W = Wop + kc * 512;
    const int rowBase = blockIdx.y * 128;
    const int colBase = blockIdx.x * 64;
    MMA_PROLOGUE
    mma_core_db(A + (size_t)rowBase * 1024, 1024, W + (size_t)colBase * 1024, 1024, 512, acc);

    float* out = partial + (size_t)kc * (1024 * 512);
#pragma unroll
    for (int mf = 0; mf < 2; mf++) {
        const int r0 = rowBase + wy * 32 + mf * 16 + g;
#pragma unroll
        for (int nt = 0; nt < 4; nt++) {
            int cb = colBase + wx * 32 + nt * 8 + 2 * t;
            *reinterpret_cast<float2*>(&out[(size_t)r0 * 512 + cb])       = make_float2(acc[mf][nt][0], acc[mf][nt][1]);
            *reinterpret_cast<float2*>(&out[(size_t)(r0 + 8) * 512 + cb]) = make_float2(acc[mf][nt][2], acc[mf][nt][3]);
        }
    }
}

__global__ void op_combine(const float* __restrict__ partial, float* __restrict__ h)
{
    int idx = blockIdx.x * 256 + threadIdx.x;          // 524288
    h[idx] += partial[idx] + partial[idx + 1024 * 512];
}

// ---------------------------------------------------------------------------
// im2col for patch embed
// ---------------------------------------------------------------------------
__global__ void im2col_kernel(const float* __restrict__ x, float* __restrict__ out)
{
    int idx = blockIdx.x * 256 + threadIdx.x;          // 1024*256
    int k = idx & 255;  int m = idx >> 8;
    int q = k & 15;     int p = k >> 4;
    int w = m & 31;     int hh = (m >> 5) & 7;  int b = m >> 8;
    out[idx] = x[((size_t)(b * 128 + hh * 16 + p) << 9) + w * 16 + q];
}

// ---------------------------------------------------------------------------
// LayerNorm: one warp per row of 512.
// ---------------------------------------------------------------------------
__global__ void ln_kernel(const float* __restrict__ x, float* __restrict__ y,
                          const float* __restrict__ w, const float* __restrict__ bsh,
                          int rows)
{
    int warp = (blockIdx.x * blockDim.x + threadIdx.x) >> 5;
    int lane = threadIdx.x & 31;
    if (warp >= rows) return;
    const float* xr = x + (size_t)warp * 512;
    float v[16]; float s = 0.f, s2 = 0.f;
#pragma unroll
    for (int i = 0; i < 16; i++) {
        float tv = xr[lane + i * 32];
        v[i] = tv; s += tv; s2 += tv * tv;
    }
#pragma unroll
    for (int o = 16; o; o >>= 1) {
        s  += __shfl_xor_sync(0xffffffffu, s, o);
        s2 += __shfl_xor_sync(0xffffffffu, s2, o);
    }
    float m   = s * (1.f / 512.f);
    float var = s2 * (1.f / 512.f) - m * m;
    float inv = rsqrtf(var + 1e-5f);
    float* yr = y + (size_t)warp * 512;
#pragma unroll
    for (int i = 0; i < 16; i++) {
        int c = lane + i * 32;
        yr[c] = (v[i] - m) * inv * w[c] + bsh[c];
    }
}

// ---------------------------------------------------------------------------
// Depthwise causal conv (K=4) + SiLU; dir=1 operates on time-flipped sequence.
// ---------------------------------------------------------------------------
__global__ void conv_silu_kernel(const float* __restrict__ xz,
                                 const float* __restrict__ cwf, const float* __restrict__ cbf,
                                 const float* __restrict__ cwb, const float* __restrict__ cbb,
                                 float* __restrict__ u0, float* __restrict__ u1)
{
    int idx = blockIdx.x * 256 + threadIdx.x;          // 0 .. 1M-1
    int dir = blockIdx.y;
    int d = idx & 1023;
    int r = idx >> 10;
    int l = r & 255;  int b = r >> 8;
    const float* cw = dir ? cwb : cwf;
    const float* cb = dir ? cbb : cbf;
    float acc = cb[d];
#pragma unroll
    for (int k = 0; k < 4; k++) {
        int p = l - 3 + k;
        if (p >= 0) {
            int torig = dir ? (255 - p) : p;
            acc += xz[((size_t)(b * 256 + torig) << 11) + d] * cw[d * 4 + k];
        }
    }
    float sg = 1.f / (1.f + __expf(-acc));
    (dir ? u1 : u0)[idx] = acc * sg;
}

// ---------------------------------------------------------------------------
// Selective scan, split-state (2 threads per channel, 8 states each),
// time unrolled x4. grid (16, 4, 2), 128 threads.
// xd row (64): dtr [0:32], B [32:48], C [48:64].
// ---------------------------------------------------------------------------
__global__ void scan_kernel(const float* __restrict__ dtbase,
                            const float* __restrict__ ubase,
                            const float* __restrict__ xdbase,
                            const float* __restrict__ Af,  const float* __restrict__ Ab,
                            const float* __restrict__ Dfp, const float* __restrict__ Dbp,
                            float* __restrict__ ybase)
{
    const int tid  = threadIdx.x;
    const int half = tid & 1;
    const int d    = blockIdx.x * 64 + (tid >> 1);
    const int b    = blockIdx.y;
    const int dir  = blockIdx.z;
    const float* dt = dtbase + (size_t)dir * (1024 * 1024);
    const float* u  = ubase  + (size_t)dir * (1024 * 1024);
    const float* xd = xdbase + (size_t)dir * (1024 * XDW);
    const float* Al = dir ? Ab  : Af;
    const float* Dp = dir ? Dbp : Dfp;
    float* y = ybase + (size_t)dir * (1024 * 1024);

    float A[8];
#pragma unroll
    for (int s = 0; s < 8; s++) A[s] = -__expf(Al[d * NS + half * 8 + s]);
    float Dv = Dp[d];
    float st[8];
#pragma unroll
    for (int s = 0; s < 8; s++) st[s] = 0.f;

    __shared__ float sBC[128];
    const size_t rowbase = (size_t)b * 256;
    for (int t0 = 0; t0 < 256; t0 += 4) {
        sBC[tid] = xd[(rowbase + t0 + (tid >> 5)) * XDW + 32 + (tid & 31)];
        __syncthreads();
        float dtv[4], uv[4];
#pragma unroll
        for (int q = 0; q < 4; q++) {
            dtv[q] = dt[(rowbase + t0 + q) * 1024 + d];
            uv[q]  = u [(rowbase + t0 + q) * 1024 + d];
        }
#pragma unroll
        for (int q = 0; q < 4; q++) {
            const float* bc = sBC + q * 32 + half * 8;
            float du = dtv[q] * uv[q];
            float yv = 0.f;
#pragma unroll
            for (int s = 0; s < 8; s++) {
                float dA = __expf(dtv[q] * A[s]);
                st[s] = st[s] * dA + du * bc[s];
                yv   += st[s] * bc[16 + s];
            }
            yv += __shfl_xor_sync(0xffffffffu, yv, 1);
            if (half == 0)
                y[(rowbase + t0 + q) * 1024 + d] = yv + uv[q] * Dv;
        }
        __syncthreads();
    }
}

// ---------------------------------------------------------------------------
// Combine: yg = (y_f + flip_L(y_b)) * silu(z)
// ---------------------------------------------------------------------------
__global__ void gate_kernel(const float* __restrict__ ybase,
                            const float* __restrict__ xz, float* __restrict__ yg)
{
    int idx = blockIdx.x * 256 + threadIdx.x;          // 1M
    int d = idx & 1023;  int r = idx >> 10;
    int l = r & 255;     int b = r >> 8;
    float z  = xz[((size_t)r << 11) + 1024 + d];
    float yv = ybase[idx] +
               ybase[1024 * 1024 + (((size_t)(b * 256) + (255 - l)) << 10) + d];
    yg[idx] = yv * (z / (1.f + __expf(-z)));
}

// ---------------------------------------------------------------------------
// Mean pool over L.
// ---------------------------------------------------------------------------
__global__ void pool_kernel(const float* __restrict__ xn, float* __restrict__ feat)
{
    int idx = blockIdx.x * 256 + threadIdx.x;          // 4*512
    if (idx >= 4 * 512) return;
    int b = idx >> 9, d = idx & 511;
    float s = 0.f;
    for (int l = 0; l < 256; l++) s += xn[((size_t)(b * 256 + l) << 9) + d];
    feat[idx] = s * (1.f / 256.f);
}

// ---------------------------------------------------------------------------
// Small FC: one warp per output element.
// ---------------------------------------------------------------------------
__global__ void fc_kernel(const float* __restrict__ in, const float* __restrict__ Wt,
                          const float* __restrict__ bias, float* __restrict__ out,
                          int Brows, int N, int K, int relu)
{
    int warp = (blockIdx.x * blockDim.x + threadIdx.x) >> 5;
    int lane = threadIdx.x & 31;
    if (warp >= Brows * N) return;
    int b = warp / N, j = warp % N;
    const float* ir = in + (size_t)b * K;
    const float* wr = Wt + (size_t)j * K;
    float s = 0.f;
    for (int k = lane; k < K; k += 32) s += ir[k] * wr[k];
#pragma unroll
    for (int o = 16; o; o >>= 1) s += __shfl_xor_sync(0xffffffffu, s, o);
    if (lane == 0) {
        float v = s + bias[j];
        if (relu) v = fmaxf(v, 0.f);
        out[warp] = v;
    }
}

// ---------------------------------------------------------------------------
// kernel_launch
// ---------------------------------------------------------------------------
extern "C" void kernel_launch(void* const* d_in, const int* in_sizes, int n_in,
                              void* d_out, int out_size)
{
    float* sc = nullptr;
    cudaGetSymbolAddress((void**)&sc, g_scratch);

    auto F = [&](int i) { return (const float*)d_in[i]; };
    const float *x = F(0), *patch_w = F(1), *patch_b = F(2), *in_proj_w = F(3);
    const float *conv_w_f, *conv_b_f, *conv_w_b, *conv_b_b;
    const float *xproj_w_f, *xproj_w_b, *dtproj_w_f, *dtproj_b_f, *dtproj_w_b, *dtproj_b_b;
    const float *A_log_f, *A_log_b, *D_f, *D_b;

    if (in_sizes[6] == 16384) {
        conv_w_f = F(4);  conv_b_f = F(5);  conv_w_b = F(6);  conv_b_b = F(7);
        xproj_w_f = F(8); xproj_w_b = F(9);
        dtproj_w_f = F(10); dtproj_b_f = F(11); dtproj_w_b = F(12); dtproj_b_b = F(13);
        A_log_f = F(14); A_log_b = F(15); D_f = F(16); D_b = F(17);
    } else {
        conv_w_f = F(4);  conv_b_f = F(5);  xproj_w_f = F(6); dtproj_w_f = F(7);
        dtproj_b_f = F(8); A_log_f = F(9);  D_f = F(10);
        conv_w_b = F(11); conv_b_b = F(12); xproj_w_b = F(13); dtproj_w_b = F(14);
        dtproj_b_b = F(15); A_log_b = F(16); D_b = F(17);
    }
    const float *out_proj_w = F(18), *norm_w = F(19), *norm_b = F(20);
    const float *normf_w = F(21), *normf_b = F(22), *ln_w = F(23), *ln_b = F(24);
    const float *fc1_w = F(25), *fc1_b = F(26), *fc2_w = F(27), *fc2_b = F(28);

    float* h_p    = sc + OFF_H;
    float* xn_p   = sc + OFF_XN;
    float* xz_p   = sc + OFF_XZ;
    float* u_p    = sc + OFF_U0;
    float* xd_p   = sc + OFF_XD0;
    float* dt_p   = sc + OFF_DT0;
    float* y_p    = sc + OFF_Y0;
    float* yg_p   = sc + OFF_YG;
    float* im_p   = sc + OFF_IM;
    float* xpp_p  = sc + OFF_XPP;
    float* opp_p  = sc + OFF_OPP;
    float* feat_p = sc + OFF_FEAT;
    float* c_p    = sc + OFF_C;
    float* f1_p   = sc + OFF_F1;

    // ---- patch embed --------------------------------------------------------
    im2col_kernel<<<1024, 256>>>(x, im_p);
    gemm32_plain<<<dim3(8, 8), 256>>>(im_p, 256, patch_w, 256, h_p, 512, 256, patch_b);

    for (int i = 0; i < 4; i++) {
        ln_kernel<<<128, 256>>>(h_p, xn_p, norm_w + i * 512, norm_b + i * 512, 1024);

        // in_proj: 1024 x 2048 x 512
        gemm32_plain<<<dim3(32, 8), 256>>>(
            xn_p, 512, in_proj_w + (size_t)i * 2048 * 512, 512, xz_p, 2048, 512, nullptr);

        conv_silu_kernel<<<dim3(4096, 2), 256>>>(
            xz_p,
            conv_w_f + i * 4096, conv_b_f + i * 1024,
            conv_w_b + i * 4096, conv_b_b + i * 1024,
            u_p, u_p + 1024 * 1024);

        gemm32_xproj_part<<<dim3(8, 8, 2), 256>>>(
            u_p, xproj_w_f + (size_t)i * XDW * 1024, xproj_w_b + (size_t)i * XDW * 1024,
            xpp_p);
        xproj_reduce<<<512, 256>>>(xpp_p, xd_p);

        gemm32_dt<<<dim3(16, 8, 2), 256>>>(
            xd_p,
            dtproj_w_f + (size_t)i * 1024 * 32, dtproj_w_b + (size_t)i * 1024 * 32,
            dtproj_b_f + i * 1024, dtproj_b_b + i * 1024,
            dt_p);

        scan_kernel<<<dim3(16, 4, 2), 128>>>(
            dt_p, u_p, xd_p,
            A_log_f + i * 16384, A_log_b + i * 16384,
            D_f + i * 1024, D_b + i * 1024,
            y_p);

        gate_kernel<<<4096, 256>>>(y_p, xz_p, yg_p);

        gemm32_op_part<<<dim3(8, 8, 2), 256>>>(
            yg_p, out_proj_w + (size_t)i * 512 * 1024, opp_p);
        op_combine<<<2048, 256>>>(opp_p, h_p);
    }

    // ---- head ---------------------------------------------------------------
    ln_kernel<<<128, 256>>>(h_p, xn_p, normf_w, normf_b, 1024);
    pool_kernel<<<8, 256>>>(xn_p, feat_p);
    ln_kernel<<<1, 256>>>(feat_p, c_p, ln_w, ln_b, 4);
    fc_kernel<<<256, 256>>>(c_p, fc1_w, fc1_b, f1_p, 4, 512, 512, 1);
    fc_kernel<<<5, 256>>>(f1_p, fc2_w, fc2_b, (float*)d_out, 4, 10, 512, 0);
}

// round 7
// speedup vs baseline: 2.9067x; 1.0418x over previous
#include <cuda_runtime.h>
#include <cstdint>
#include <cstddef>

// ---------------------------------------------------------------------------
// AudioMamba forward on GB300 — R7: wide (128x128) tf32 MMA core for the big
// GEMMs + dt_proj fused into the scan.
// ---------------------------------------------------------------------------

constexpr int NS = 16;
constexpr int XDW = 64;

// ---- scratch --------------------------------------------------------------
constexpr size_t OFF_H    = 0;
constexpr size_t OFF_XN   = OFF_H    + 1024 * 512;
constexpr size_t OFF_XZ   = OFF_XN   + 1024 * 512;
constexpr size_t OFF_U0   = OFF_XZ   + 1024 * 2048;
constexpr size_t OFF_XD0  = OFF_U0   + 2 * 1024 * 1024;
constexpr size_t OFF_Y0   = OFF_XD0  + 2 * 1024 * XDW;
constexpr size_t OFF_YG   = OFF_Y0   + 2 * 1024 * 1024;
constexpr size_t OFF_IM   = OFF_YG   + 1024 * 1024;
constexpr size_t OFF_XPP  = OFF_IM   + 1024 * 256;
constexpr size_t OFF_OPP  = OFF_XPP  + 16 * 1024 * 64;   // 4 x 1024 x 512
constexpr size_t OFF_FEAT = OFF_OPP  + 4 * 1024 * 512;
constexpr size_t OFF_C    = OFF_FEAT + 4 * 512;
constexpr size_t OFF_F1   = OFF_C    + 4 * 512;
constexpr size_t SCRATCH_FLOATS = OFF_F1 + 4 * 512;

__device__ __align__(16) float g_scratch[SCRATCH_FLOATS];

// ---------------------------------------------------------------------------
// tf32 helpers
// ---------------------------------------------------------------------------
__device__ __forceinline__ float f2tf32(float f) {
    uint32_t u;
    asm("cvt.rna.tf32.f32 %0, %1;" : "=r"(u) : "f"(f));
    return __uint_as_float(u);
}
__device__ __forceinline__ float4 cvt4(float4 v) {
    return make_float4(f2tf32(v.x), f2tf32(v.y), f2tf32(v.z), f2tf32(v.w));
}

__device__ __forceinline__ void mma_tf32(float& c0, float& c1, float& c2, float& c3,
                                         uint32_t a0, uint32_t a1, uint32_t a2, uint32_t a3,
                                         uint32_t b0, uint32_t b1)
{
    asm volatile(
        "mma.sync.aligned.m16n8k8.row.col.f32.tf32.tf32.f32 "
        "{%0,%1,%2,%3}, {%4,%5,%6,%7}, {%8,%9}, {%0,%1,%2,%3};\n"
        : "+f"(c0), "+f"(c1), "+f"(c2), "+f"(c3)
        : "r"(a0), "r"(a1), "r"(a2), "r"(a3), "r"(b0), "r"(b1));
}

// ===========================================================================
// WIDE core: 128x128 block tile, BK=16, 256 threads, warp tile 32x64.
// wy = warp>>1 (0..3) -> rows wy*32; wx = warp&1 -> cols wx*64.
// acc[mf in 0..1][nt in 0..7][4]. Frag: c0(r,c) c1(r,c+1) c2(r+8,c) c3(r+8,c+1),
//   r = wy*32+mf*16+lane/4, c = wx*64+nt*8+2*(lane%4).
// ===========================================================================
__device__ __forceinline__ void mma_core_wide(const float* __restrict__ Ab, int lda,
                                              const float* __restrict__ Wb, int ldw,
                                              int kend, float (&acc)[2][8][4])
{
    __shared__ __align__(16) float As[2][128][20];
    __shared__ __align__(16) float Bs[2][128][20];

    const int tid  = threadIdx.x;
    const int warp = tid >> 5, lane = tid & 31;
    const int wy = warp >> 1, wx = warp & 1;
    const int g = lane >> 2, t = lane & 3;

    const int row = tid >> 1, col = (tid & 1) * 8;   // 2 thr/row, 8 floats each

    {
        float4 a0 = *reinterpret_cast<const float4*>(Ab + (size_t)row * lda + col);
        float4 a1 = *reinterpret_cast<const float4*>(Ab + (size_t)row * lda + col + 4);
        float4 b0 = *reinterpret_cast<const float4*>(Wb + (size_t)row * ldw + col);
        float4 b1 = *reinterpret_cast<const float4*>(Wb + (size_t)row * ldw + col + 4);
        *reinterpret_cast<float4*>(&As[0][row][col])     = cvt4(a0);
        *reinterpret_cast<float4*>(&As[0][row][col + 4]) = cvt4(a1);
        *reinterpret_cast<float4*>(&Bs[0][row][col])     = cvt4(b0);
        *reinterpret_cast<float4*>(&Bs[0][row][col + 4]) = cvt4(b1);
    }
    __syncthreads();

    const int niter = kend >> 4;
    for (int it = 0; it < niter; it++) {
        const int cur = it & 1;
        float4 pa0, pa1, pb0, pb1;
        const bool more = (it + 1 < niter);
        if (more) {
            int k0 = (it + 1) << 4;
            pa0 = *reinterpret_cast<const float4*>(Ab + (size_t)row * lda + k0 + col);
            pa1 = *reinterpret_cast<const float4*>(Ab + (size_t)row * lda + k0 + col + 4);
            pb0 = *reinterpret_cast<const float4*>(Wb + (size_t)row * ldw + k0 + col);
            pb1 = *reinterpret_cast<const float4*>(Wb + (size_t)row * ldw + k0 + col + 4);
        }

#pragma unroll
        for (int k8 = 0; k8 < 16; k8 += 8) {
            uint32_t a[2][4];
#pragma unroll
            for (int mf = 0; mf < 2; mf++) {
                const int ar = wy * 32 + mf * 16 + g;
                a[mf][0] = __float_as_uint(As[cur][ar][k8 + t]);
                a[mf][1] = __float_as_uint(As[cur][ar + 8][k8 + t]);
                a[mf][2] = __float_as_uint(As[cur][ar][k8 + t + 4]);
                a[mf][3] = __float_as_uint(As[cur][ar + 8][k8 + t + 4]);
            }
#pragma unroll
            for (int nt = 0; nt < 8; nt++) {
                const int bn = wx * 64 + nt * 8 + g;
                uint32_t b0 = __float_as_uint(Bs[cur][bn][k8 + t]);
                uint32_t b1 = __float_as_uint(Bs[cur][bn][k8 + t + 4]);
#pragma unroll
                for (int mf = 0; mf < 2; mf++)
                    mma_tf32(acc[mf][nt][0], acc[mf][nt][1], acc[mf][nt][2], acc[mf][nt][3],
                             a[mf][0], a[mf][1], a[mf][2], a[mf][3], b0, b1);
            }
        }

        if (more) {
            const int nxt = cur ^ 1;
            *reinterpret_cast<float4*>(&As[nxt][row][col])     = cvt4(pa0);
            *reinterpret_cast<float4*>(&As[nxt][row][col + 4]) = cvt4(pa1);
            *reinterpret_cast<float4*>(&Bs[nxt][row][col])     = cvt4(pb0);
            *reinterpret_cast<float4*>(&Bs[nxt][row][col + 4]) = cvt4(pb1);
            __syncthreads();
        }
    }
}

#define WIDE_PROLOGUE                                             \
    const int warp = threadIdx.x >> 5, lane = threadIdx.x & 31;   \
    const int wy = warp >> 1, wx = warp & 1;                      \
    const int g = lane >> 2, t = lane & 3;                        \
    float acc[2][8][4];                                           \
    _Pragma("unroll")                                             \
    for (int i = 0; i < 2; i++)                                   \
        _Pragma("unroll")                                         \
        for (int j = 0; j < 8; j++)                               \
            _Pragma("unroll")                                     \
            for (int q = 0; q < 4; q++) acc[i][j][q] = 0.f;

// in_proj / generic wide GEMM: C = A*W^T. grid (N/128, M/128).
__global__ void __launch_bounds__(256)
gemm32_wide(const float* __restrict__ A, int lda,
            const float* __restrict__ W, int ldw,
            float* __restrict__ C, int ldc, int K)
{
    const int rowBase = blockIdx.y * 128;
    const int colBase = blockIdx.x * 128;
    WIDE_PROLOGUE
    mma_core_wide(A + (size_t)rowBase * lda, lda, W + (size_t)colBase * ldw, ldw, K, acc);

#pragma unroll
    for (int mf = 0; mf < 2; mf++) {
        const int r0 = rowBase + wy * 32 + mf * 16 + g;
#pragma unroll
        for (int nt = 0; nt < 8; nt++) {
            int cb = colBase + wx * 64 + nt * 8 + 2 * t;
            *reinterpret_cast<float2*>(&C[(size_t)r0 * ldc + cb])       = make_float2(acc[mf][nt][0], acc[mf][nt][1]);
            *reinterpret_cast<float2*>(&C[(size_t)(r0 + 8) * ldc + cb]) = make_float2(acc[mf][nt][2], acc[mf][nt][3]);
        }
    }
}

// out_proj partial, split-K(4): grid (4 n, 8 m, 4 kc). K-chunk 256.
__global__ void __launch_bounds__(256)
gemm32_op_wide(const float* __restrict__ yg, const float* __restrict__ Wop,
               float* __restrict__ partial)
{
    const int kc = blockIdx.z;
    const float* A = yg + kc * 256;
    const float* W = Wop + kc * 256;
    const int rowBase = blockIdx.y * 128;
    const int colBase = blockIdx.x * 128;
    WIDE_PROLOGUE
    mma_core_wide(A + (size_t)rowBase * 1024, 1024, W + (size_t)colBase * 1024, 1024, 256, acc);

    float* out = partial + (size_t)kc * (1024 * 512);
#pragma unroll
    for (int mf = 0; mf < 2; mf++) {
        const int r0 = rowBase + wy * 32 + mf * 16 + g;
#pragma unroll
        for (int nt = 0; nt < 8; nt++) {
            int cb = colBase + wx * 64 + nt * 8 + 2 * t;
            *reinterpret_cast<float2*>(&out[(size_t)r0 * 512 + cb])       = make_float2(acc[mf][nt][0], acc[mf][nt][1]);
            *reinterpret_cast<float2*>(&out[(size_t)(r0 + 8) * 512 + cb]) = make_float2(acc[mf][nt][2], acc[mf][nt][3]);
        }
    }
}

__global__ void op_combine(const float* __restrict__ partial, float* __restrict__ h)
{
    int idx = blockIdx.x * 256 + threadIdx.x;          // 524288
    h[idx] += partial[idx] + partial[idx + 1024 * 512]
            + partial[idx + 2 * 1024 * 512] + partial[idx + 3 * 1024 * 512];
}

// ===========================================================================
// 64-wide core (128x64 tile) — for patch embed and x_proj (N=64).
// ===========================================================================
__device__ __forceinline__ void mma_core_db(const float* __restrict__ Ab, int lda,
                                            const float* __restrict__ Wb, int ldw,
                                            int kend, float (&acc)[2][4][4])
{
    __shared__ __align__(16) float As[2][128][20];
    __shared__ __align__(16) float Bs[2][64][20];

    const int tid  = threadIdx.x;
    const int warp = tid >> 5, lane = tid & 31;
    const int wy = warp >> 1, wx = warp & 1;
    const int g = lane >> 2, t = lane & 3;

    const int arow = tid >> 1, acol = (tid & 1) * 8;
    const int brow = tid >> 2, bcol = (tid & 3) * 4;

    {
        float4 va0 = *reinterpret_cast<const float4*>(Ab + (size_t)arow * lda + acol);
        float4 va1 = *reinterpret_cast<const float4*>(Ab + (size_t)arow * lda + acol + 4);
        float4 vb  = *reinterpret_cast<const float4*>(Wb + (size_t)brow * ldw + bcol);
        *reinterpret_cast<float4*>(&As[0][arow][acol])     = cvt4(va0);
        *reinterpret_cast<float4*>(&As[0][arow][acol + 4]) = cvt4(va1);
        *reinterpret_cast<float4*>(&Bs[0][brow][bcol])     = cvt4(vb);
    }
    __syncthreads();

    const int niter = kend >> 4;
    for (int it = 0; it < niter; it++) {
        const int cur = it & 1;
        float4 pa0, pa1, pb;
        const bool more = (it + 1 < niter);
        if (more) {
            int k0 = (it + 1) << 4;
            pa0 = *reinterpret_cast<const float4*>(Ab + (size_t)arow * lda + k0 + acol);
            pa1 = *reinterpret_cast<const float4*>(Ab + (size_t)arow * lda + k0 + acol + 4);
            pb  = *reinterpret_cast<const float4*>(Wb + (size_t)brow * ldw + k0 + bcol);
        }

#pragma unroll
        for (int k8 = 0; k8 < 16; k8 += 8) {
            uint32_t a[2][4], b[4][2];
#pragma unroll
            for (int mf = 0; mf < 2; mf++) {
                const int ar = wy * 32 + mf * 16 + g;
                a[mf][0] = __float_as_uint(As[cur][ar][k8 + t]);
                a[mf][1] = __float_as_uint(As[cur][ar + 8][k8 + t]);
                a[mf][2] = __float_as_uint(As[cur][ar][k8 + t + 4]);
                a[mf][3] = __float_as_uint(As[cur][ar + 8][k8 + t + 4]);
            }
#pragma unroll
            for (int nt = 0; nt < 4; nt++) {
                const int bn = wx * 32 + nt * 8 + g;
                b[nt][0] = __float_as_uint(Bs[cur][bn][k8 + t]);
                b[nt][1] = __float_as_uint(Bs[cur][bn][k8 + t + 4]);
            }
#pragma unroll
            for (int mf = 0; mf < 2; mf++)
#pragma unroll
                for (int nt = 0; nt < 4; nt++)
                    mma_tf32(acc[mf][nt][0], acc[mf][nt][1], acc[mf][nt][2], acc[mf][nt][3],
                             a[mf][0], a[mf][1], a[mf][2], a[mf][3],
                             b[nt][0], b[nt][1]);
        }

        if (more) {
            const int nxt = cur ^ 1;
            *reinterpret_cast<float4*>(&As[nxt][arow][acol])     = cvt4(pa0);
            *reinterpret_cast<float4*>(&As[nxt][arow][acol + 4]) = cvt4(pa1);
            *reinterpret_cast<float4*>(&Bs[nxt][brow][bcol])     = cvt4(pb);
            __syncthreads();
        }
    }
}

#define MMA_PROLOGUE                                              \
    const int warp = threadIdx.x >> 5, lane = threadIdx.x & 31;   \
    const int wy = warp >> 1, wx = warp & 1;                      \
    const int g = lane >> 2, t = lane & 3;                        \
    float acc[2][4][4];                                           \
    _Pragma("unroll")                                             \
    for (int i = 0; i < 2; i++)                                   \
        _Pragma("unroll")                                         \
        for (int j = 0; j < 4; j++)                               \
            _Pragma("unroll")                                     \
            for (int q = 0; q < 4; q++) acc[i][j][q] = 0.f;

// patch embed GEMM (with bias): grid (N/64, M/128).
__global__ void __launch_bounds__(256)
gemm32_plain(const float* __restrict__ A, int lda,
             const float* __restrict__ W, int ldw,
             float* __restrict__ C, int ldc, int K,
             const float* __restrict__ bias)
{
    const int rowBase = blockIdx.y * 128;
    const int colBase = blockIdx.x * 64;
    MMA_PROLOGUE
    mma_core_db(A + (size_t)rowBase * lda, lda, W + (size_t)colBase * ldw, ldw, K, acc);

#pragma unroll
    for (int mf = 0; mf < 2; mf++) {
        const int r0 = rowBase + wy * 32 + mf * 16 + g;
#pragma unroll
        for (int nt = 0; nt < 4; nt++) {
            int cb = colBase + wx * 32 + nt * 8 + 2 * t;
            float v0 = acc[mf][nt][0], v1 = acc[mf][nt][1];
            float v2 = acc[mf][nt][2], v3 = acc[mf][nt][3];
            if (bias) { v0 += bias[cb]; v1 += bias[cb + 1]; v2 += bias[cb]; v3 += bias[cb + 1]; }
            *reinterpret_cast<float2*>(&C[(size_t)r0 * ldc + cb])       = make_float2(v0, v1);
            *reinterpret_cast<float2*>(&C[(size_t)(r0 + 8) * ldc + cb]) = make_float2(v2, v3);
        }
    }
}

// x_proj partial, split-K(8) + dir-batched: grid (8 kc, 8 m, 2 dir). N=64.
__global__ void __launch_bounds__(256)
gemm32_xproj_part(const float* __restrict__ ubase,
                  const float* __restrict__ W0, const float* __restrict__ W1,
                  float* __restrict__ partial)
{
    const int kc  = blockIdx.x;
    const int dir = blockIdx.z;
    const float* A = ubase + (size_t)dir * (1024 * 1024) + kc * 128;
    const float* W = (dir ? W1 : W0) + kc * 128;
    const int rowBase = blockIdx.y * 128;
    MMA_PROLOGUE
    mma_core_db(A + (size_t)rowBase * 1024, 1024, W, 1024, 128, acc);

    float* out = partial + ((size_t)(dir * 8 + kc)) * (1024 * 64);
#pragma unroll
    for (int mf = 0; mf < 2; mf++) {
        const int r0 = rowBase + wy * 32 + mf * 16 + g;
#pragma unroll
        for (int nt = 0; nt < 4; nt++) {
            int cb = wx * 32 + nt * 8 + 2 * t;
            *reinterpret_cast<float2*>(&out[(size_t)r0 * 64 + cb])       = make_float2(acc[mf][nt][0], acc[mf][nt][1]);
            *reinterpret_cast<float2*>(&out[(size_t)(r0 + 8) * 64 + cb]) = make_float2(acc[mf][nt][2], acc[mf][nt][3]);
        }
    }
}

__global__ void xproj_reduce(const float* __restrict__ partial, float* __restrict__ xdbase)
{
    int idx = blockIdx.x * 256 + threadIdx.x;          // 2*65536
    int dir = idx >> 16;
    int rem = idx & 65535;
    float s = 0.f;
#pragma unroll
    for (int kc = 0; kc < 8; kc++)
        s += partial[((size_t)(dir * 8 + kc) << 16) + rem];
    xdbase[((size_t)dir << 16) + rem] = s;
}

// ---------------------------------------------------------------------------
// im2col for patch embed
// ---------------------------------------------------------------------------
__global__ void im2col_kernel(const float* __restrict__ x, float* __restrict__ out)
{
    int idx = blockIdx.x * 256 + threadIdx.x;          // 1024*256
    int k = idx & 255;  int m = idx >> 8;
    int q = k & 15;     int p = k >> 4;
    int w = m & 31;     int hh = (m >> 5) & 7;  int b = m >> 8;
    out[idx] = x[((size_t)(b * 128 + hh * 16 + p) << 9) + w * 16 + q];
}

// ---------------------------------------------------------------------------
// LayerNorm: one warp per row of 512.
// ---------------------------------------------------------------------------
__global__ void ln_kernel(const float* __restrict__ x, float* __restrict__ y,
                          const float* __restrict__ w, const float* __restrict__ bsh,
                          int rows)
{
    int warp = (blockIdx.x * blockDim.x + threadIdx.x) >> 5;
    int lane = threadIdx.x & 31;
    if (warp >= rows) return;
    const float* xr = x + (size_t)warp * 512;
    float v[16]; float s = 0.f, s2 = 0.f;
#pragma unroll
    for (int i = 0; i < 16; i++) {
        float tv = xr[lane + i * 32];
        v[i] = tv; s += tv; s2 += tv * tv;
    }
#pragma unroll
    for (int o = 16; o; o >>= 1) {
        s  += __shfl_xor_sync(0xffffffffu, s, o);
        s2 += __shfl_xor_sync(0xffffffffu, s2, o);
    }
    float m   = s * (1.f / 512.f);
    float var = s2 * (1.f / 512.f) - m * m;
    float inv = rsqrtf(var + 1e-5f);
    float* yr = y + (size_t)warp * 512;
#pragma unroll
    for (int i = 0; i < 16; i++) {
        int c = lane + i * 32;
        yr[c] = (v[i] - m) * inv * w[c] + bsh[c];
    }
}

// ---------------------------------------------------------------------------
// Depthwise causal conv (K=4) + SiLU; dir=1 operates on time-flipped sequence.
// ---------------------------------------------------------------------------
__global__ void conv_silu_kernel(const float* __restrict__ xz,
                                 const float* __restrict__ cwf, const float* __restrict__ cbf,
                                 const float* __restrict__ cwb, const float* __restrict__ cbb,
                                 float* __restrict__ u0, float* __restrict__ u1)
{
    int idx = blockIdx.x * 256 + threadIdx.x;          // 0 .. 1M-1
    int dir = blockIdx.y;
    int d = idx & 1023;
    int r = idx >> 10;
    int l = r & 255;  int b = r >> 8;
    const float* cw = dir ? cwb : cwf;
    const float* cb = dir ? cbb : cbf;
    float acc = cb[d];
#pragma unroll
    for (int k = 0; k < 4; k++) {
        int p = l - 3 + k;
        if (p >= 0) {
            int torig = dir ? (255 - p) : p;
            acc += xz[((size_t)(b * 256 + torig) << 11) + d] * cw[d * 4 + k];
        }
    }
    float sg = 1.f / (1.f + __expf(-acc));
    (dir ? u1 : u0)[idx] = acc * sg;
}

// ---------------------------------------------------------------------------
// Selective scan with FUSED dt_proj+softplus. Split-state: 2 threads per
// channel x 8 states. grid (16, 4, 2), 128 threads.
// xd row (64): dtr [0:32], B [32:48], C [48:64].
// dt[t][d] = softplus( dot(xd[t][0:32], dtw[d][:]) + dtb[d] ).
// ---------------------------------------------------------------------------
__global__ void scan_kernel(const float* __restrict__ ubase,
                            const float* __restrict__ xdbase,
                            const float* __restrict__ dtw0, const float* __restrict__ dtw1,
                            const float* __restrict__ dtb0, const float* __restrict__ dtb1,
                            const float* __restrict__ Af,  const float* __restrict__ Ab,
                            const float* __restrict__ Dfp, const float* __restrict__ Dbp,
                            float* __restrict__ ybase)
{
    const int tid  = threadIdx.x;
    const int half = tid & 1;
    const int d    = blockIdx.x * 64 + (tid >> 1);
    const int b    = blockIdx.y;
    const int dir  = blockIdx.z;
    const float* u  = ubase  + (size_t)dir * (1024 * 1024);
    const float* xd = xdbase + (size_t)dir * (1024 * XDW);
    const float* dtw = (dir ? dtw1 : dtw0) + d * 32 + half * 16;
    const float  dtb = (dir ? dtb1 : dtb0)[d];
    const float* Al = dir ? Ab  : Af;
    const float* Dp = dir ? Dbp : Dfp;
    float* y = ybase + (size_t)dir * (1024 * 1024);

    float w[16];
#pragma unroll
    for (int i = 0; i < 16; i++) w[i] = dtw[i];
    float A[8];
#pragma unroll
    for (int s = 0; s < 8; s++) A[s] = -__expf(Al[d * NS + half * 8 + s]);
    float Dv = Dp[d];
    float st[8];
#pragma unroll
    for (int s = 0; s < 8; s++) st[s] = 0.f;

    __shared__ float sXD[256];           // 4 time steps x full 64-wide xd row
    const size_t rowbase = (size_t)b * 256;
    for (int t0 = 0; t0 < 256; t0 += 4) {
        sXD[tid]       = xd[(rowbase + t0 + (tid >> 6)) * XDW + (tid & 63)];
        sXD[tid + 128] = xd[(rowbase + t0 + 2 + (tid >> 6)) * XDW + (tid & 63)];
        __syncthreads();
        float uv[4];
#pragma unroll
        for (int q = 0; q < 4; q++)
            uv[q] = u[(rowbase + t0 + q) * 1024 + d];
#pragma unroll
        for (int q = 0; q < 4; q++) {
            const float* xr = sXD + q * 64;
            // fused dt_proj: half-dot then pair-sum
            float dot = 0.f;
#pragma unroll
            for (int i = 0; i < 16; i++) dot = fmaf(w[i], xr[half * 16 + i], dot);
            dot += __shfl_xor_sync(0xffffffffu, dot, 1);
            float dtv = dot + dtb;
            dtv = (dtv > 20.f) ? dtv : log1pf(__expf(dtv));

            const float* bc = xr + 32 + half * 8;    // B half; C at +16
            float du = dtv * uv[q];
            float yv = 0.f;
#pragma unroll
            for (int s = 0; s < 8; s++) {
                float dA = __expf(dtv * A[s]);
                st[s] = st[s] * dA + du * bc[s];
                yv   += st[s] * bc[16 + s];
            }
            yv += __shfl_xor_sync(0xffffffffu, yv, 1);
            if (half == 0)
                y[(rowbase + t0 + q) * 1024 + d] = yv + uv[q] * Dv;
        }
        __syncthreads();
    }
}

// ---------------------------------------------------------------------------
// Combine: yg = (y_f + flip_L(y_b)) * silu(z)
// ---------------------------------------------------------------------------
__global__ void gate_kernel(const float* __restrict__ ybase,
                            const float* __restrict__ xz, float* __restrict__ yg)
{
    int idx = blockIdx.x * 256 + threadIdx.x;          // 1M
    int d = idx & 1023;  int r = idx >> 10;
    int l = r & 255;     int b = r >> 8;
    float z  = xz[((size_t)r << 11) + 1024 + d];
    float yv = ybase[idx] +
               ybase[1024 * 1024 + (((size_t)(b * 256) + (255 - l)) << 10) + d];
    yg[idx] = yv * (z / (1.f + __expf(-z)));
}

// ---------------------------------------------------------------------------
// Mean pool over L.
// ---------------------------------------------------------------------------
__global__ void pool_kernel(const float* __restrict__ xn, float* __restrict__ feat)
{
    int idx = blockIdx.x * 256 + threadIdx.x;          // 4*512
    if (idx >= 4 * 512) return;
    int b = idx >> 9, d = idx & 511;
    float s = 0.f;
    for (int l = 0; l < 256; l++) s += xn[((size_t)(b * 256 + l) << 9) + d];
    feat[idx] = s * (1.f / 256.f);
}

// ---------------------------------------------------------------------------
// Small FC: one warp per output element.
// ---------------------------------------------------------------------------
__global__ void fc_kernel(const float* __restrict__ in, const float* __restrict__ Wt,
                          const float* __restrict__ bias, float* __restrict__ out,
                          int Brows, int N, int K, int relu)
{
    int warp = (blockIdx.x * blockDim.x + threadIdx.x) >> 5;
    int lane = threadIdx.x & 31;
    if (warp >= Brows * N) return;
    int b = warp / N, j = warp % N;
    const float* ir = in + (size_t)b * K;
    const float* wr = Wt + (size_t)j * K;
    float s = 0.f;
    for (int k = lane; k < K; k += 32) s += ir[k] * wr[k];
#pragma unroll
    for (int o = 16; o; o >>= 1) s += __shfl_xor_sync(0xffffffffu, s, o);
    if (lane == 0) {
        float v = s + bias[j];
        if (relu) v = fmaxf(v, 0.f);
        out[warp] = v;
    }
}

// ---------------------------------------------------------------------------
// kernel_launch
// ---------------------------------------------------------------------------
extern "C" void kernel_launch(void* const* d_in, const int* in_sizes, int n_in,
                              void* d_out, int out_size)
{
    float* sc = nullptr;
    cudaGetSymbolAddress((void**)&sc, g_scratch);

    auto F = [&](int i) { return (const float*)d_in[i]; };
    const float *x = F(0), *patch_w = F(1), *patch_b = F(2), *in_proj_w = F(3);
    const float *conv_w_f, *conv_b_f, *conv_w_b, *conv_b_b;
    const float *xproj_w_f, *xproj_w_b, *dtproj_w_f, *dtproj_b_f, *dtproj_w_b, *dtproj_b_b;
    const float *A_log_f, *A_log_b, *D_f, *D_b;

    if (in_sizes[6] == 16384) {
        conv_w_f = F(4);  conv_b_f = F(5);  conv_w_b = F(6);  conv_b_b = F(7);
        xproj_w_f = F(8); xproj_w_b = F(9);
        dtproj_w_f = F(10); dtproj_b_f = F(11); dtproj_w_b = F(12); dtproj_b_b = F(13);
        A_log_f = F(14); A_log_b = F(15); D_f = F(16); D_b = F(17);
    } else {
        conv_w_f = F(4);  conv_b_f = F(5);  xproj_w_f = F(6); dtproj_w_f = F(7);
        dtproj_b_f = F(8); A_log_f = F(9);  D_f = F(10);
        conv_w_b = F(11); conv_b_b = F(12); xproj_w_b = F(13); dtproj_w_b = F(14);
        dtproj_b_b = F(15); A_log_b = F(16); D_b = F(17);
    }
    const float *out_proj_w = F(18), *norm_w = F(19), *norm_b = F(20);
    const float *normf_w = F(21), *normf_b = F(22), *ln_w = F(23), *ln_b = F(24);
    const float *fc1_w = F(25), *fc1_b = F(26), *fc2_w = F(27), *fc2_b = F(28);

    float* h_p    = sc + OFF_H;
    float* xn_p   = sc + OFF_XN;
    float* xz_p   = sc + OFF_XZ;
    float* u_p    = sc + OFF_U0;
    float* xd_p   = sc + OFF_XD0;
    float* y_p    = sc + OFF_Y0;
    float* yg_p   = sc + OFF_YG;
    float* im_p   = sc + OFF_IM;
    float* xpp_p  = sc + OFF_XPP;
    float* opp_p  = sc + OFF_OPP;
    float* feat_p = sc + OFF_FEAT;
    float* c_p    = sc + OFF_C;
    float* f1_p   = sc + OFF_F1;

    // ---- patch embed --------------------------------------------------------
    im2col_kernel<<<1024, 256>>>(x, im_p);
    gemm32_plain<<<dim3(8, 8), 256>>>(im_p, 256, patch_w, 256, h_p, 512, 256, patch_b);

    for (int i = 0; i < 4; i++) {
        ln_kernel<<<128, 256>>>(h_p, xn_p, norm_w + i * 512, norm_b + i * 512, 1024);

        // in_proj: 1024 x 2048 x 512 (wide core, grid 16x8 = 128 blocks)
        gemm32_wide<<<dim3(16, 8), 256>>>(
            xn_p, 512, in_proj_w + (size_t)i * 2048 * 512, 512, xz_p, 2048, 512);

        conv_silu_kernel<<<dim3(4096, 2), 256>>>(
            xz_p,
            conv_w_f + i * 4096, conv_b_f + i * 1024,
            conv_w_b + i * 4096, conv_b_b + i * 1024,
            u_p, u_p + 1024 * 1024);

        gemm32_xproj_part<<<dim3(8, 8, 2), 256>>>(
            u_p, xproj_w_f + (size_t)i * XDW * 1024, xproj_w_b + (size_t)i * XDW * 1024,
            xpp_p);
        xproj_reduce<<<512, 256>>>(xpp_p, xd_p);

        // scan with fused dt_proj
        scan_kernel<<<dim3(16, 4, 2), 128>>>(
            u_p, xd_p,
            dtproj_w_f + (size_t)i * 1024 * 32, dtproj_w_b + (size_t)i * 1024 * 32,
            dtproj_b_f + i * 1024, dtproj_b_b + i * 1024,
            A_log_f + i * 16384, A_log_b + i * 16384,
            D_f + i * 1024, D_b + i * 1024,
            y_p);

        gate_kernel<<<4096, 256>>>(y_p, xz_p, yg_p);

        // out_proj: wide core, split-K(4), grid (4,8,4) = 128 blocks
        gemm32_op_wide<<<dim3(4, 8, 4), 256>>>(
            yg_p, out_proj_w + (size_t)i * 512 * 1024, opp_p);
        op_combine<<<2048, 256>>>(opp_p, h_p);
    }

    // ---- head ---------------------------------------------------------------
    ln_kernel<<<128, 256>>>(h_p, xn_p, normf_w, normf_b, 1024);
    pool_kernel<<<8, 256>>>(xn_p, feat_p);
    ln_kernel<<<1, 256>>>(feat_p, c_p, ln_w, ln_b, 4);
    fc_kernel<<<256, 256>>>(c_p, fc1_w, fc1_b, f1_p, 4, 512, 512, 1);
    fc_kernel<<<5, 256>>>(f1_p, fc2_w, fc2_b, (float*)d_out, 4, 10, 512, 0);
}